// round 2
// baseline (speedup 1.0000x reference)
#include <cuda_runtime.h>
#include <math.h>

#define S_LEN 2048
#define EDIM 1024
#define NHEAD 16
#define HD 64
#define BATCH 2
#define MROWS (BATCH * S_LEN)        // 4096
#define ATT_SCALE (1.0f / 64.0f)     // 1/head_dim per reference

// Scratch (device globals; no allocations allowed)
__device__ float g_q[BATCH * NHEAD * S_LEN * HD];   // [B,H,S,hd], pre-scaled by ATT_SCALE
__device__ float g_k[BATCH * NHEAD * S_LEN * HD];
__device__ float g_v[BATCH * NHEAD * S_LEN * HD];
__device__ float g_attn[MROWS * EDIM];              // [B,S,D]

// ---------------------------------------------------------------------------
// GEMM: C[M=4096, N=1024] = A[4096,1024] @ W[1024,1024] + bias
// 64x64 block tile, BK=16, 256 threads, 4x4 per thread.
// mode 0: plain row-major store. mode 1: scatter to [B,H,S,hd] with scale.
// ---------------------------------------------------------------------------
__global__ __launch_bounds__(256) void gemm64(const float* __restrict__ A,
                                              const float* __restrict__ W,
                                              const float* __restrict__ bias,
                                              float* __restrict__ C,
                                              int mode, float scale)
{
    __shared__ float As[16][68];   // [k][m] transposed, padded
    __shared__ float Bs[16][64];   // [k][n]

    const int tid = threadIdx.x;
    const int tx = tid & 15;
    const int ty = tid >> 4;
    const int m0 = blockIdx.y << 6;
    const int n0 = blockIdx.x << 6;

    // load assignments
    const int ar = tid >> 2;            // A row within tile (0..63)
    const int ac = (tid & 3) << 2;      // A k-offset (0,4,8,12)
    const int br = tid >> 4;            // W k-row within tile (0..15)
    const int bc = (tid & 15) << 2;     // W n-offset (0..60)

    const float* Aptr = A + (size_t)(m0 + ar) * EDIM + ac;
    const float* Wptr = W + (size_t)br * EDIM + n0 + bc;

    float4 a4 = *(const float4*)Aptr;
    float4 b4 = *(const float4*)Wptr;

    float acc[4][4];
#pragma unroll
    for (int i = 0; i < 4; i++)
#pragma unroll
        for (int j = 0; j < 4; j++) acc[i][j] = 0.0f;

    for (int k0 = 0; k0 < EDIM; k0 += 16) {
        As[ac + 0][ar] = a4.x;
        As[ac + 1][ar] = a4.y;
        As[ac + 2][ar] = a4.z;
        As[ac + 3][ar] = a4.w;
        *(float4*)&Bs[br][bc] = b4;
        __syncthreads();

        if (k0 + 16 < EDIM) {
            a4 = *(const float4*)(Aptr + k0 + 16);
            b4 = *(const float4*)(Wptr + (size_t)(k0 + 16) * EDIM);
        }

#pragma unroll
        for (int kk = 0; kk < 16; kk++) {
            float af[4];
#pragma unroll
            for (int i = 0; i < 4; i++) af[i] = As[kk][(ty << 2) + i];
            float4 bf = *(const float4*)&Bs[kk][tx << 2];
#pragma unroll
            for (int i = 0; i < 4; i++) {
                acc[i][0] += af[i] * bf.x;
                acc[i][1] += af[i] * bf.y;
                acc[i][2] += af[i] * bf.z;
                acc[i][3] += af[i] * bf.w;
            }
        }
        __syncthreads();
    }

    const int nbase = n0 + (tx << 2);
    float4 bias4 = *(const float4*)&bias[nbase];

    if (mode == 0) {
#pragma unroll
        for (int i = 0; i < 4; i++) {
            const int m = m0 + (ty << 2) + i;
            float4 o = make_float4(acc[i][0] + bias4.x, acc[i][1] + bias4.y,
                                   acc[i][2] + bias4.z, acc[i][3] + bias4.w);
            *(float4*)&C[(size_t)m * EDIM + nbase] = o;
        }
    } else {
        // scatter to [B,H,S,hd]; one block column == one head
        const int h = blockIdx.x;      // n0 = h*64
        const int d = tx << 2;
#pragma unroll
        for (int i = 0; i < 4; i++) {
            const int m = m0 + (ty << 2) + i;
            const int b = m >> 11;             // m / S_LEN
            const int s = m & (S_LEN - 1);
            float4 o = make_float4((acc[i][0] + bias4.x) * scale,
                                   (acc[i][1] + bias4.y) * scale,
                                   (acc[i][2] + bias4.z) * scale,
                                   (acc[i][3] + bias4.w) * scale);
            size_t dst = ((size_t)((b * NHEAD + h) * S_LEN + s)) * HD + d;
            *(float4*)&C[dst] = o;
        }
    }
}

// ---------------------------------------------------------------------------
// Flash attention, mask allows j >= i (reversed causal).
// grid: (32 q-blocks, 32 batch*head), 256 threads. 64x64 tiles.
// Q pre-scaled by ATT_SCALE. Output written as [B,S,D].
// ---------------------------------------------------------------------------
__global__ __launch_bounds__(256) void flash64(const float* __restrict__ Q,
                                               const float* __restrict__ K,
                                               const float* __restrict__ V,
                                               float* __restrict__ O)
{
    __shared__ float Qs[64][64];   // [q_row][hd]
    __shared__ float KP[64][64];   // K^T: [hd][key]; reused as P: [q_row][key]
    __shared__ float Vs[64][64];   // [key][hd]

    const int tid = threadIdx.x;
    const int tx = tid & 15;
    const int ty = tid >> 4;
    const int qb = blockIdx.x;
    const int bh = blockIdx.y;
    const int q0 = qb << 6;
    const size_t base = (size_t)bh * S_LEN * HD;

    // load Q tile (coalesced-ish float4)
    {
        const int r = tid >> 2;
        const int seg = (tid & 3) << 4;
        const float* src = Q + base + (size_t)(q0 + r) * HD + seg;
#pragma unroll
        for (int u = 0; u < 4; u++)
            *(float4*)&Qs[r][seg + (u << 2)] = *(const float4*)(src + (u << 2));
    }

    float m_i[4], l_i[4], acc[4][4];
#pragma unroll
    for (int i = 0; i < 4; i++) {
        m_i[i] = -INFINITY;
        l_i[i] = 0.0f;
#pragma unroll
        for (int j = 0; j < 4; j++) acc[i][j] = 0.0f;
    }

    for (int kb = qb; kb < S_LEN / 64; kb++) {
        const int k0 = kb << 6;

        // load K transposed into KP[hd][key] (conflict-free smem writes)
        {
            const int key = tid & 63;
            const int hdb = (tid >> 6) << 4;
            const float* src = K + base + (size_t)(k0 + key) * HD + hdb;
#pragma unroll
            for (int u = 0; u < 4; u++) {
                float4 kv = *(const float4*)(src + (u << 2));
                KP[hdb + (u << 2) + 0][key] = kv.x;
                KP[hdb + (u << 2) + 1][key] = kv.y;
                KP[hdb + (u << 2) + 2][key] = kv.z;
                KP[hdb + (u << 2) + 3][key] = kv.w;
            }
        }
        // load V
        {
            const int r = tid >> 2;
            const int seg = (tid & 3) << 4;
            const float* src = V + base + (size_t)(k0 + r) * HD + seg;
#pragma unroll
            for (int u = 0; u < 4; u++)
                *(float4*)&Vs[r][seg + (u << 2)] = *(const float4*)(src + (u << 2));
        }
        __syncthreads();

        // S = Q @ K^T  (Q pre-scaled)
        float sacc[4][4];
#pragma unroll
        for (int i = 0; i < 4; i++)
#pragma unroll
            for (int j = 0; j < 4; j++) sacc[i][j] = 0.0f;

#pragma unroll 4
        for (int k = 0; k < 64; k++) {
            float af[4];
#pragma unroll
            for (int i = 0; i < 4; i++) af[i] = Qs[(ty << 2) + i][k];
            float4 bf = *(const float4*)&KP[k][tx << 2];
#pragma unroll
            for (int i = 0; i < 4; i++) {
                sacc[i][0] += af[i] * bf.x;
                sacc[i][1] += af[i] * bf.y;
                sacc[i][2] += af[i] * bf.z;
                sacc[i][3] += af[i] * bf.w;
            }
        }

        // mask on diagonal block: keep j >= i
        if (kb == qb) {
#pragma unroll
            for (int i = 0; i < 4; i++) {
                const int ri = (ty << 2) + i;
#pragma unroll
                for (int j = 0; j < 4; j++)
                    if (((tx << 2) + j) < ri) sacc[i][j] = -INFINITY;
            }
        }

        // online softmax update (rows owned by 16-lane groups)
        float fac[4];
#pragma unroll
        for (int i = 0; i < 4; i++) {
            float rmax = fmaxf(fmaxf(sacc[i][0], sacc[i][1]),
                               fmaxf(sacc[i][2], sacc[i][3]));
#pragma unroll
            for (int off = 8; off > 0; off >>= 1)
                rmax = fmaxf(rmax, __shfl_xor_sync(0xffffffffu, rmax, off));
            const float mn = fmaxf(m_i[i], rmax);
            float rs = 0.0f;
#pragma unroll
            for (int j = 0; j < 4; j++) {
                sacc[i][j] = __expf(sacc[i][j] - mn);   // P in place
                rs += sacc[i][j];
            }
#pragma unroll
            for (int off = 8; off > 0; off >>= 1)
                rs += __shfl_xor_sync(0xffffffffu, rs, off);
            fac[i] = __expf(m_i[i] - mn);
            l_i[i] = l_i[i] * fac[i] + rs;
            m_i[i] = mn;
#pragma unroll
            for (int j = 0; j < 4; j++) acc[i][j] *= fac[i];
        }

        __syncthreads();   // everyone done reading K from KP
        // store P into KP as [q_row][key]
#pragma unroll
        for (int i = 0; i < 4; i++)
            *(float4*)&KP[(ty << 2) + i][tx << 2] =
                make_float4(sacc[i][0], sacc[i][1], sacc[i][2], sacc[i][3]);
        __syncthreads();

        // O += P @ V
#pragma unroll 4
        for (int kk = 0; kk < 64; kk++) {
            float pf[4];
#pragma unroll
            for (int i = 0; i < 4; i++) pf[i] = KP[(ty << 2) + i][kk];
            float4 vf = *(const float4*)&Vs[kk][tx << 2];
#pragma unroll
            for (int i = 0; i < 4; i++) {
                acc[i][0] += pf[i] * vf.x;
                acc[i][1] += pf[i] * vf.y;
                acc[i][2] += pf[i] * vf.z;
                acc[i][3] += pf[i] * vf.w;
            }
        }
        __syncthreads();   // before next tile overwrites KP/Vs
    }

    // write output [B,S,D]
    const int b = bh >> 4;
    const int h = bh & 15;
#pragma unroll
    for (int i = 0; i < 4; i++) {
        const int s = q0 + (ty << 2) + i;
        const float inv = 1.0f / l_i[i];
        float4 o = make_float4(acc[i][0] * inv, acc[i][1] * inv,
                               acc[i][2] * inv, acc[i][3] * inv);
        *(float4*)&O[((size_t)(b * S_LEN + s)) * EDIM + (h << 6) + (tx << 2)] = o;
    }
}

// ---------------------------------------------------------------------------
extern "C" void kernel_launch(void* const* d_in, const int* in_sizes, int n_in,
                              void* d_out, int out_size)
{
    (void)in_sizes; (void)n_in; (void)out_size;
    const float* x  = (const float*)d_in[0];
    const float* wq = (const float*)d_in[1];
    const float* bq = (const float*)d_in[2];
    const float* wk = (const float*)d_in[3];
    const float* bk = (const float*)d_in[4];
    const float* wv = (const float*)d_in[5];
    const float* bv = (const float*)d_in[6];
    const float* wo = (const float*)d_in[7];
    const float* bo = (const float*)d_in[8];
    float* out = (float*)d_out;

    float *qp, *kp, *vp, *ap;
    cudaGetSymbolAddress((void**)&qp, g_q);
    cudaGetSymbolAddress((void**)&kp, g_k);
    cudaGetSymbolAddress((void**)&vp, g_v);
    cudaGetSymbolAddress((void**)&ap, g_attn);

    dim3 ggrid(EDIM / 64, MROWS / 64);   // (16, 64)
    gemm64<<<ggrid, 256>>>(x, wq, bq, qp, 1, ATT_SCALE);
    gemm64<<<ggrid, 256>>>(x, wk, bk, kp, 1, 1.0f);
    gemm64<<<ggrid, 256>>>(x, wv, bv, vp, 1, 1.0f);

    dim3 fgrid(S_LEN / 64, BATCH * NHEAD);   // (32, 32)
    flash64<<<fgrid, 256>>>(qp, kp, vp, ap);

    gemm64<<<ggrid, 256>>>(ap, wo, bo, out, 0, 1.0f);
}

// round 5
// speedup vs baseline: 2.0452x; 2.0452x over previous
#include <cuda_runtime.h>
#include <math.h>
#include <stdint.h>

#define S_LEN 2048
#define EDIM 1024
#define NHEAD 16
#define HD 64
#define BATCH 2
#define MROWS (BATCH * S_LEN)        // 4096
// softmax done in exp2 domain: fold 1/head_dim * log2(e) into Q projection
#define QSCALE (1.4426950408889634f / 64.0f)

// Scratch (device globals; no allocations allowed)
__device__ float g_q[BATCH * NHEAD * S_LEN * HD];   // [B,H,S,hd], pre-scaled
__device__ float g_k[BATCH * NHEAD * S_LEN * HD];
__device__ float g_v[BATCH * NHEAD * S_LEN * HD];
__device__ float g_attn[MROWS * EDIM];              // [B,S,D]

// ---------------------------------------------------------------------------
// helpers
// ---------------------------------------------------------------------------
__device__ __forceinline__ uint32_t cvt_tf32(float x) {
    uint32_t r;
    asm("cvt.rna.tf32.f32 %0, %1;" : "=r"(r) : "f"(x));
    return r;
}

__device__ __forceinline__ float ex2f(float x) {
    float y;
    asm("ex2.approx.ftz.f32 %0, %1;" : "=f"(y) : "f"(x));
    return y;
}

__device__ __forceinline__ void ldm4(uint32_t* r, uint32_t addr) {
    asm volatile("ldmatrix.sync.aligned.m8n8.x4.shared.b16 {%0,%1,%2,%3}, [%4];"
                 : "=r"(r[0]), "=r"(r[1]), "=r"(r[2]), "=r"(r[3]) : "r"(addr));
}

// c += A(16x8,tf32) * B(8x8,tf32); a-operand regs in (a0,a1,a2,a3) order
__device__ __forceinline__ void mma8(float* c, uint32_t a0, uint32_t a1,
                                     uint32_t a2, uint32_t a3,
                                     uint32_t b0, uint32_t b1) {
    asm volatile(
        "mma.sync.aligned.m16n8k8.row.col.f32.tf32.tf32.f32 "
        "{%0,%1,%2,%3}, {%4,%5,%6,%7}, {%8,%9}, {%0,%1,%2,%3};\n"
        : "+f"(c[0]), "+f"(c[1]), "+f"(c[2]), "+f"(c[3])
        : "r"(a0), "r"(a1), "r"(a2), "r"(a3), "r"(b0), "r"(b1));
}

// ---------------------------------------------------------------------------
// GEMM: C[4096,1024] = A @ W + bias, tf32 tensor cores.
// 128x128 block, BK=32, 256 threads (8 warps, 2x4), warp tile 64x32.
// mode 0: row-major store. mode 1: scatter to [B,H,S,hd] with scale.
// ---------------------------------------------------------------------------
__global__ __launch_bounds__(256) void gemm_tc(const float* __restrict__ A,
                                               const float* __restrict__ W,
                                               const float* __restrict__ bias,
                                               float* __restrict__ C,
                                               int mode, float scale)
{
    __shared__ uint32_t As[128 * 36];   // [m][k], pad 36 (16B-aligned rows)
    __shared__ uint32_t Bs[128 * 36];   // [n][k] (W transposed)

    const int tid = threadIdx.x;
    const int lane = tid & 31;
    const int wid = tid >> 5;
    const int wm = wid & 1;             // 2 warps along M
    const int wn = wid >> 1;            // 4 warps along N
    const int m0 = blockIdx.y << 7;
    const int n0 = blockIdx.x << 7;

    // ldmatrix per-lane offsets (A-style, also used for B since layout matches)
    const int row_off = (lane & 7) + ((lane & 16) >> 1);  // +8 for grp 2,3
    const int k_off = (lane & 8) >> 1;                     // +4 for odd grp

    const uint32_t asA = (uint32_t)__cvta_generic_to_shared(As);
    const uint32_t asB = (uint32_t)__cvta_generic_to_shared(Bs);

    // global load assignments
    const int ar = tid >> 1;               // A row 0..127
    const int akc = (tid & 1) << 4;        // A k offset 0/16
    const int bkr = tid >> 3;              // W k row 0..31
    const int bnc = (tid & 7) << 4;        // W n offset 0..112

    const float* Ap = A + (size_t)(m0 + ar) * EDIM + akc;
    const float* Wp = W + (size_t)bkr * EDIM + n0 + bnc;

    float4 af[4], bf[4];
#pragma unroll
    for (int u = 0; u < 4; u++) {
        af[u] = *(const float4*)(Ap + (u << 2));
        bf[u] = *(const float4*)(Wp + (u << 2));
    }

    float acc[4][4][4];
#pragma unroll
    for (int i = 0; i < 4; i++)
#pragma unroll
        for (int j = 0; j < 4; j++)
#pragma unroll
            for (int c = 0; c < 4; c++) acc[i][j][c] = 0.0f;

    for (int k0 = 0; k0 < EDIM; k0 += 32) {
        // store A tile (tf32), row-major
#pragma unroll
        for (int u = 0; u < 4; u++) {
            uint4 t;
            t.x = cvt_tf32(af[u].x); t.y = cvt_tf32(af[u].y);
            t.z = cvt_tf32(af[u].z); t.w = cvt_tf32(af[u].w);
            *(uint4*)&As[ar * 36 + akc + (u << 2)] = t;
        }
        // store W tile transposed -> Bs[n][k]
#pragma unroll
        for (int u = 0; u < 4; u++) {
            const int nb = bnc + (u << 2);
            Bs[(nb + 0) * 36 + bkr] = cvt_tf32(bf[u].x);
            Bs[(nb + 1) * 36 + bkr] = cvt_tf32(bf[u].y);
            Bs[(nb + 2) * 36 + bkr] = cvt_tf32(bf[u].z);
            Bs[(nb + 3) * 36 + bkr] = cvt_tf32(bf[u].w);
        }
        __syncthreads();

        if (k0 + 32 < EDIM) {
#pragma unroll
            for (int u = 0; u < 4; u++) {
                af[u] = *(const float4*)(Ap + k0 + 32 + (u << 2));
                bf[u] = *(const float4*)(Wp + (size_t)(k0 + 32) * EDIM + (u << 2));
            }
        }

#pragma unroll
        for (int ks = 0; ks < 32; ks += 8) {
            uint32_t a[4][4], b[2][4];
#pragma unroll
            for (int i = 0; i < 4; i++)
                ldm4(a[i], asA + (((wm << 6) + (i << 4) + row_off) * 36 + ks + k_off) * 4);
#pragma unroll
            for (int j = 0; j < 2; j++)
                ldm4(b[j], asB + (((wn << 5) + (j << 4) + row_off) * 36 + ks + k_off) * 4);
#pragma unroll
            for (int i = 0; i < 4; i++)
#pragma unroll
                for (int j = 0; j < 4; j++)
                    mma8(acc[i][j], a[i][0], a[i][2], a[i][1], a[i][3],
                         b[j >> 1][(j & 1) << 1], b[j >> 1][((j & 1) << 1) + 1]);
        }
        __syncthreads();
    }

    // epilogue: c0,c1 at (row tq, col 2tr..+1); c2,c3 at row tq+8
    const int tq = lane >> 2;
    const int tr = lane & 3;
#pragma unroll
    for (int i = 0; i < 4; i++) {
#pragma unroll
        for (int j = 0; j < 4; j++) {
            const int row = m0 + (wm << 6) + (i << 4) + tq;
            const int col = n0 + (wn << 5) + (j << 3) + (tr << 1);
            const float b0 = bias[col], b1 = bias[col + 1];
            if (mode == 0) {
                *(float2*)&C[(size_t)row * EDIM + col] =
                    make_float2(acc[i][j][0] + b0, acc[i][j][1] + b1);
                *(float2*)&C[(size_t)(row + 8) * EDIM + col] =
                    make_float2(acc[i][j][2] + b0, acc[i][j][3] + b1);
            } else {
                const int h = col >> 6, d = col & 63;
#pragma unroll
                for (int rr = 0; rr < 2; rr++) {
                    const int r = row + (rr << 3);
                    const int bb = r >> 11;
                    const int s = r & (S_LEN - 1);
                    size_t dst = ((size_t)((bb * NHEAD + h) * S_LEN + s)) * HD + d;
                    *(float2*)&C[dst] = make_float2(
                        (acc[i][j][(rr << 1) + 0] + b0) * scale,
                        (acc[i][j][(rr << 1) + 1] + b1) * scale);
                }
            }
        }
    }
}

// ---------------------------------------------------------------------------
// Flash attention (mask keeps j >= i), tf32 tensor cores.
// Bq=Bk=64, 128 threads (4 warps), each warp owns 16 q rows.
// Q fragments live in registers. KQ buffer: Q load -> K tiles -> P tiles.
// ---------------------------------------------------------------------------
__global__ __launch_bounds__(128) void flash_tc(const float* __restrict__ Q,
                                                const float* __restrict__ K,
                                                const float* __restrict__ V,
                                                float* __restrict__ O)
{
    __shared__ uint32_t KQ[64 * 68];   // Q, then per-tile K, then P (tf32)
    __shared__ uint32_t Vt[64 * 68];   // V transposed: [d][key]

    const int tid = threadIdx.x;
    const int lane = tid & 31;
    const int wid = tid >> 5;          // 0..3
    const int qb = blockIdx.x;
    const int bh = blockIdx.y;
    const int q0 = qb << 6;
    const size_t base = (size_t)bh * S_LEN * HD;

    const int row_off = (lane & 7) + ((lane & 16) >> 1);
    const int k_off = (lane & 8) >> 1;
    const int tq = lane >> 2;
    const int tr = lane & 3;

    const uint32_t sKQ = (uint32_t)__cvta_generic_to_shared(KQ);
    const uint32_t sVt = (uint32_t)__cvta_generic_to_shared(Vt);

    const int lrow = tid >> 1;               // 0..63
    const int lcol = (tid & 1) << 5;         // 0/32

    // load Q tile -> KQ (tf32)
    {
        const float* src = Q + base + (size_t)(q0 + lrow) * HD + lcol;
#pragma unroll
        for (int u = 0; u < 8; u++) {
            float4 v = *(const float4*)(src + (u << 2));
            uint4 t;
            t.x = cvt_tf32(v.x); t.y = cvt_tf32(v.y);
            t.z = cvt_tf32(v.z); t.w = cvt_tf32(v.w);
            *(uint4*)&KQ[lrow * 68 + lcol + (u << 2)] = t;
        }
    }
    __syncthreads();

    // Q fragments for the warp's 16 rows, all 8 k-steps
    uint32_t qa[8][4];
#pragma unroll
    for (int ks = 0; ks < 8; ks++)
        ldm4(qa[ks], sKQ + (((wid << 4) + row_off) * 68 + (ks << 3) + k_off) * 4);

    float o[8][4];
#pragma unroll
    for (int j = 0; j < 8; j++)
#pragma unroll
        for (int c = 0; c < 4; c++) o[j][c] = 0.0f;
    float m0 = -INFINITY, m1 = -INFINITY, l0 = 0.0f, l1 = 0.0f;

    for (int kb = qb; kb < S_LEN / 64; kb++) {
        __syncthreads();   // Q frags / previous P@V reads complete
        const int k0g = kb << 6;

        // load K tile -> KQ (row-major [key][d], tf32)
        {
            const float* src = K + base + (size_t)(k0g + lrow) * HD + lcol;
#pragma unroll
            for (int u = 0; u < 8; u++) {
                float4 v = *(const float4*)(src + (u << 2));
                uint4 t;
                t.x = cvt_tf32(v.x); t.y = cvt_tf32(v.y);
                t.z = cvt_tf32(v.z); t.w = cvt_tf32(v.w);
                *(uint4*)&KQ[lrow * 68 + lcol + (u << 2)] = t;
            }
        }
        // load V tile -> Vt (transposed [d][key], tf32)
        {
            const float* src = V + base + (size_t)(k0g + lrow) * HD + lcol;
#pragma unroll
            for (int u = 0; u < 8; u++) {
                float4 v = *(const float4*)(src + (u << 2));
                const int d = lcol + (u << 2);
                Vt[(d + 0) * 68 + lrow] = cvt_tf32(v.x);
                Vt[(d + 1) * 68 + lrow] = cvt_tf32(v.y);
                Vt[(d + 2) * 68 + lrow] = cvt_tf32(v.z);
                Vt[(d + 3) * 68 + lrow] = cvt_tf32(v.w);
            }
        }
        __syncthreads();

        // S = Q @ K^T (in exp2 domain; Q pre-scaled by 1/hd*log2e)
        float s[8][4];
#pragma unroll
        for (int j = 0; j < 8; j++)
#pragma unroll
            for (int c = 0; c < 4; c++) s[j][c] = 0.0f;

#pragma unroll
        for (int ks = 0; ks < 8; ks++) {
            uint32_t b[4][4];
#pragma unroll
            for (int j2 = 0; j2 < 4; j2++)
                ldm4(b[j2], sKQ + (((j2 << 4) + row_off) * 68 + (ks << 3) + k_off) * 4);
#pragma unroll
            for (int j = 0; j < 8; j++)
                mma8(s[j], qa[ks][0], qa[ks][2], qa[ks][1], qa[ks][3],
                     b[j >> 1][(j & 1) << 1], b[j >> 1][((j & 1) << 1) + 1]);
        }

        // mask diagonal block: keep key >= q
        if (kb == qb) {
            const int r0l = (wid << 4) + tq;
#pragma unroll
            for (int j = 0; j < 8; j++) {
                const int c0 = (j << 3) + (tr << 1);
                if (c0 < r0l)     s[j][0] = -INFINITY;
                if (c0 + 1 < r0l) s[j][1] = -INFINITY;
                if (c0 < r0l + 8)     s[j][2] = -INFINITY;
                if (c0 + 1 < r0l + 8) s[j][3] = -INFINITY;
            }
        }

        // online softmax (rows tq and tq+8; replicated across 4 lanes)
        float rmax0 = -INFINITY, rmax1 = -INFINITY;
#pragma unroll
        for (int j = 0; j < 8; j++) {
            rmax0 = fmaxf(rmax0, fmaxf(s[j][0], s[j][1]));
            rmax1 = fmaxf(rmax1, fmaxf(s[j][2], s[j][3]));
        }
#pragma unroll
        for (int off = 1; off <= 2; off <<= 1) {
            rmax0 = fmaxf(rmax0, __shfl_xor_sync(0xffffffffu, rmax0, off));
            rmax1 = fmaxf(rmax1, __shfl_xor_sync(0xffffffffu, rmax1, off));
        }
        const float mn0 = fmaxf(m0, rmax0);
        const float mn1 = fmaxf(m1, rmax1);
        const float fac0 = ex2f(m0 - mn0);
        const float fac1 = ex2f(m1 - mn1);
        float sum0 = 0.0f, sum1 = 0.0f;
#pragma unroll
        for (int j = 0; j < 8; j++) {
            s[j][0] = ex2f(s[j][0] - mn0);
            s[j][1] = ex2f(s[j][1] - mn0);
            s[j][2] = ex2f(s[j][2] - mn1);
            s[j][3] = ex2f(s[j][3] - mn1);
            sum0 += s[j][0] + s[j][1];
            sum1 += s[j][2] + s[j][3];
        }
#pragma unroll
        for (int off = 1; off <= 2; off <<= 1) {
            sum0 += __shfl_xor_sync(0xffffffffu, sum0, off);
            sum1 += __shfl_xor_sync(0xffffffffu, sum1, off);
        }
        l0 = l0 * fac0 + sum0;  m0 = mn0;
        l1 = l1 * fac1 + sum1;  m1 = mn1;
#pragma unroll
        for (int j = 0; j < 8; j++) {
            o[j][0] *= fac0; o[j][1] *= fac0;
            o[j][2] *= fac1; o[j][3] *= fac1;
        }

        __syncthreads();   // all warps finished reading K from KQ
        // store P (tf32) into own 16 rows of KQ
#pragma unroll
        for (int j = 0; j < 8; j++) {
            const int cb = (j << 3) + (tr << 1);
            const int r0 = (wid << 4) + tq;
            KQ[r0 * 68 + cb]     = cvt_tf32(s[j][0]);
            KQ[r0 * 68 + cb + 1] = cvt_tf32(s[j][1]);
            KQ[(r0 + 8) * 68 + cb]     = cvt_tf32(s[j][2]);
            KQ[(r0 + 8) * 68 + cb + 1] = cvt_tf32(s[j][3]);
        }
        __syncwarp();

        // O += P @ V
#pragma unroll
        for (int ks = 0; ks < 8; ks++) {
            uint32_t pa[4], b[4][4];
            ldm4(pa, sKQ + (((wid << 4) + row_off) * 68 + (ks << 3) + k_off) * 4);
#pragma unroll
            for (int j2 = 0; j2 < 4; j2++)
                ldm4(b[j2], sVt + (((j2 << 4) + row_off) * 68 + (ks << 3) + k_off) * 4);
#pragma unroll
            for (int j = 0; j < 8; j++)
                mma8(o[j], pa[0], pa[2], pa[1], pa[3],
                     b[j >> 1][(j & 1) << 1], b[j >> 1][((j & 1) << 1) + 1]);
        }
    }

    // epilogue: normalize and write [B,S,D]
    const float inv0 = 1.0f / l0;
    const float inv1 = 1.0f / l1;
    const int b = bh >> 4;
    const int h = bh & 15;
    const int r0g = q0 + (wid << 4) + tq;
#pragma unroll
    for (int j = 0; j < 8; j++) {
        const int col = (h << 6) + (j << 3) + (tr << 1);
        *(float2*)&O[((size_t)(b * S_LEN + r0g)) * EDIM + col] =
            make_float2(o[j][0] * inv0, o[j][1] * inv0);
        *(float2*)&O[((size_t)(b * S_LEN + r0g + 8)) * EDIM + col] =
            make_float2(o[j][2] * inv1, o[j][3] * inv1);
    }
}

// ---------------------------------------------------------------------------
extern "C" void kernel_launch(void* const* d_in, const int* in_sizes, int n_in,
                              void* d_out, int out_size)
{
    (void)in_sizes; (void)n_in; (void)out_size;
    const float* x  = (const float*)d_in[0];
    const float* wq = (const float*)d_in[1];
    const float* bq = (const float*)d_in[2];
    const float* wk = (const float*)d_in[3];
    const float* bk = (const float*)d_in[4];
    const float* wv = (const float*)d_in[5];
    const float* bv = (const float*)d_in[6];
    const float* wo = (const float*)d_in[7];
    const float* bo = (const float*)d_in[8];
    float* out = (float*)d_out;

    float *qp, *kp, *vp, *ap;
    cudaGetSymbolAddress((void**)&qp, g_q);
    cudaGetSymbolAddress((void**)&kp, g_k);
    cudaGetSymbolAddress((void**)&vp, g_v);
    cudaGetSymbolAddress((void**)&ap, g_attn);

    dim3 ggrid(EDIM / 128, MROWS / 128);   // (8, 32)
    gemm_tc<<<ggrid, 256>>>(x, wq, bq, qp, 1, QSCALE);
    gemm_tc<<<ggrid, 256>>>(x, wk, bk, kp, 1, 1.0f);
    gemm_tc<<<ggrid, 256>>>(x, wv, bv, vp, 1, 1.0f);

    dim3 fgrid(S_LEN / 64, BATCH * NHEAD);   // (32, 32)
    flash_tc<<<fgrid, 128>>>(qp, kp, vp, ap);

    gemm_tc<<<ggrid, 256>>>(ap, wo, bo, out, 0, 1.0f);
}

// round 7
// speedup vs baseline: 2.6291x; 1.2855x over previous
#include <cuda_runtime.h>
#include <math.h>
#include <stdint.h>

#define S_LEN 2048
#define EDIM 1024
#define NHEAD 16
#define HD 64
#define BATCH 2
#define MROWS (BATCH * S_LEN)        // 4096
// softmax done in exp2 domain: fold 1/head_dim * log2(e) into Q projection
#define QSCALE (1.4426950408889634f / 64.0f)

// Scratch (device globals; no allocations allowed)
__device__ float g_q[BATCH * NHEAD * S_LEN * HD];   // [B,H,S,hd], pre-scaled
__device__ float g_k[BATCH * NHEAD * S_LEN * HD];
__device__ float g_v[BATCH * NHEAD * S_LEN * HD];
__device__ float g_attn[MROWS * EDIM];              // [B,S,D]

// ---------------------------------------------------------------------------
// helpers
// ---------------------------------------------------------------------------
__device__ __forceinline__ uint32_t cvt_tf32(float x) {
    uint32_t r;
    asm("cvt.rna.tf32.f32 %0, %1;" : "=r"(r) : "f"(x));
    return r;
}

__device__ __forceinline__ float ex2f(float x) {
    float y;
    asm("ex2.approx.ftz.f32 %0, %1;" : "=f"(y) : "f"(x));
    return y;
}

__device__ __forceinline__ void ldm4(uint32_t* r, uint32_t addr) {
    asm volatile("ldmatrix.sync.aligned.m8n8.x4.shared.b16 {%0,%1,%2,%3}, [%4];"
                 : "=r"(r[0]), "=r"(r[1]), "=r"(r[2]), "=r"(r[3]) : "r"(addr));
}

// c += A(16x8,tf32) * B(8x8,tf32); a0..a3 in PTX fragment order
__device__ __forceinline__ void mma8(float* c, uint32_t a0, uint32_t a1,
                                     uint32_t a2, uint32_t a3,
                                     uint32_t b0, uint32_t b1) {
    asm volatile(
        "mma.sync.aligned.m16n8k8.row.col.f32.tf32.tf32.f32 "
        "{%0,%1,%2,%3}, {%4,%5,%6,%7}, {%8,%9}, {%0,%1,%2,%3};\n"
        : "+f"(c[0]), "+f"(c[1]), "+f"(c[2]), "+f"(c[3])
        : "r"(a0), "r"(a1), "r"(a2), "r"(a3), "r"(b0), "r"(b1));
}

// ---------------------------------------------------------------------------
// GEMM: C[4096,1024] = A @ W + bias, tf32 tensor cores.
// 128x128 block, BK=32, 256 threads (8 warps, 2x4), warp tile 64x32.
// A: row-major smem + ldmatrix. B: K-MAJOR smem (conflict-free float4 stores)
// + LDS.32 fragment loads (conflict-free, exact PTX b-frag layout).
// mode 0: plain row-major store. mode 1: scatter to [B,H,S,hd] with scale.
// ---------------------------------------------------------------------------
__global__ __launch_bounds__(256) void gemm_tc(const float* __restrict__ A,
                                               const float* __restrict__ W,
                                               const float* __restrict__ bias,
                                               float* __restrict__ C,
                                               int mode, float scale)
{
    __shared__ uint32_t As[128 * 36];   // [m][k], pad 36
    __shared__ uint32_t Bs[32 * 132];   // [k][n], pad 132

    const int tid = threadIdx.x;
    const int lane = tid & 31;
    const int wid = tid >> 5;
    const int wm = wid & 1;             // 2 warps along M
    const int wn = wid >> 1;            // 4 warps along N
    const int m0 = blockIdx.y << 7;
    const int n0 = blockIdx.x << 7;

    const int row_off = (lane & 7) + ((lane & 16) >> 1);
    const int k_off = (lane & 8) >> 1;
    const int cB = lane & 3;            // b-frag k row
    const int gB = lane >> 2;           // b-frag n col

    const uint32_t asA = (uint32_t)__cvta_generic_to_shared(As);

    // global load assignments
    const int ar = tid >> 1;               // A row 0..127
    const int akc = (tid & 1) << 4;        // A k offset 0/16
    const int bkr = tid >> 3;              // W k row 0..31
    const int bnc = (tid & 7) << 4;        // W n offset 0..112

    const float* Ap = A + (size_t)(m0 + ar) * EDIM + akc;
    const float* Wp = W + (size_t)bkr * EDIM + n0 + bnc;

    float4 af[4], bf[4];
#pragma unroll
    for (int u = 0; u < 4; u++) {
        af[u] = *(const float4*)(Ap + (u << 2));
        bf[u] = *(const float4*)(Wp + (u << 2));
    }

    float acc[4][4][4];
#pragma unroll
    for (int i = 0; i < 4; i++)
#pragma unroll
        for (int j = 0; j < 4; j++)
#pragma unroll
            for (int c = 0; c < 4; c++) acc[i][j][c] = 0.0f;

    const uint32_t* bbase = Bs + (wn << 5) + gB;

    for (int k0 = 0; k0 < EDIM; k0 += 32) {
        // store A tile (tf32), row-major
#pragma unroll
        for (int u = 0; u < 4; u++) {
            uint4 t;
            t.x = cvt_tf32(af[u].x); t.y = cvt_tf32(af[u].y);
            t.z = cvt_tf32(af[u].z); t.w = cvt_tf32(af[u].w);
            *(uint4*)&As[ar * 36 + akc + (u << 2)] = t;
        }
        // store W tile k-major (natural layout, conflict-free)
#pragma unroll
        for (int u = 0; u < 4; u++) {
            uint4 t;
            t.x = cvt_tf32(bf[u].x); t.y = cvt_tf32(bf[u].y);
            t.z = cvt_tf32(bf[u].z); t.w = cvt_tf32(bf[u].w);
            *(uint4*)&Bs[bkr * 132 + bnc + (u << 2)] = t;
        }
        __syncthreads();

        if (k0 + 32 < EDIM) {
#pragma unroll
            for (int u = 0; u < 4; u++) {
                af[u] = *(const float4*)(Ap + k0 + 32 + (u << 2));
                bf[u] = *(const float4*)(Wp + (size_t)(k0 + 32) * EDIM + (u << 2));
            }
        }

#pragma unroll
        for (int ks = 0; ks < 32; ks += 8) {
            uint32_t a[4][4];
#pragma unroll
            for (int i = 0; i < 4; i++)
                ldm4(a[i], asA + (((wm << 6) + (i << 4) + row_off) * 36 + ks + k_off) * 4);
            uint32_t b[4][2];
#pragma unroll
            for (int j = 0; j < 4; j++) {
                b[j][0] = bbase[(ks + cB) * 132 + (j << 3)];
                b[j][1] = bbase[(ks + cB + 4) * 132 + (j << 3)];
            }
#pragma unroll
            for (int i = 0; i < 4; i++)
#pragma unroll
                for (int j = 0; j < 4; j++)
                    mma8(acc[i][j], a[i][0], a[i][2], a[i][1], a[i][3],
                         b[j][0], b[j][1]);
        }
        __syncthreads();
    }

    // epilogue: c0,c1 at (row tq, col 2tr..+1); c2,c3 at row tq+8
    const int tq = lane >> 2;
    const int tr = lane & 3;
#pragma unroll
    for (int i = 0; i < 4; i++) {
#pragma unroll
        for (int j = 0; j < 4; j++) {
            const int row = m0 + (wm << 6) + (i << 4) + tq;
            const int col = n0 + (wn << 5) + (j << 3) + (tr << 1);
            const float b0 = bias[col], b1 = bias[col + 1];
            if (mode == 0) {
                *(float2*)&C[(size_t)row * EDIM + col] =
                    make_float2(acc[i][j][0] + b0, acc[i][j][1] + b1);
                *(float2*)&C[(size_t)(row + 8) * EDIM + col] =
                    make_float2(acc[i][j][2] + b0, acc[i][j][3] + b1);
            } else {
                const int h = col >> 6, d = col & 63;
#pragma unroll
                for (int rr = 0; rr < 2; rr++) {
                    const int r = row + (rr << 3);
                    const int bb = r >> 11;
                    const int s = r & (S_LEN - 1);
                    size_t dst = ((size_t)((bb * NHEAD + h) * S_LEN + s)) * HD + d;
                    *(float2*)&C[dst] = make_float2(
                        (acc[i][j][(rr << 1) + 0] + b0) * scale,
                        (acc[i][j][(rr << 1) + 1] + b1) * scale);
                }
            }
        }
    }
}

// ---------------------------------------------------------------------------
// Flash attention (mask keeps j >= i), tf32 tensor cores.
// Bq=Bk=64, 128 threads (4 warps), each warp owns 16 q rows.
// Q fragments loaded DIRECTLY from global into PTX register order (no smem).
// P stays in registers: V is stored with keys permuted {0,2,4,6,1,3,5,7}
// within each 8-group so the S accumulator layout == A fragment layout.
// ---------------------------------------------------------------------------
__global__ __launch_bounds__(128) void flash_tc(const float* __restrict__ Q,
                                                const float* __restrict__ K,
                                                const float* __restrict__ V,
                                                float* __restrict__ O)
{
    __shared__ uint32_t Ks[64 * 68];   // K: [key][d] tf32
    __shared__ uint32_t Vt[64 * 68];   // V^T: [d][key-slot] tf32, permuted cols

    const int tid = threadIdx.x;
    const int lane = tid & 31;
    const int wid = tid >> 5;          // 0..3
    const int qb = blockIdx.x;
    const int bh = blockIdx.y;
    const int q0 = qb << 6;
    const size_t base = (size_t)bh * S_LEN * HD;

    const int row_off = (lane & 7) + ((lane & 16) >> 1);
    const int k_off = (lane & 8) >> 1;
    const int tq = lane >> 2;
    const int tr = lane & 3;

    const uint32_t sKs = (uint32_t)__cvta_generic_to_shared(Ks);
    const uint32_t sVt = (uint32_t)__cvta_generic_to_shared(Vt);

    const int lrow = tid >> 1;               // 0..63
    const int lcol = (tid & 1) << 5;         // 0/32

    // Q fragments straight from global, PTX order (a0,a1,a2,a3)
    uint32_t qa[8][4];
    {
        const float* Qb = Q + base + (size_t)(q0 + (wid << 4) + tq) * HD;
#pragma unroll
        for (int ks = 0; ks < 8; ks++) {
            qa[ks][0] = cvt_tf32(Qb[(ks << 3) + tr]);
            qa[ks][1] = cvt_tf32(Qb[(HD << 3) + (ks << 3) + tr]);
            qa[ks][2] = cvt_tf32(Qb[(ks << 3) + tr + 4]);
            qa[ks][3] = cvt_tf32(Qb[(HD << 3) + (ks << 3) + tr + 4]);
        }
    }

    float o[8][4];
#pragma unroll
    for (int j = 0; j < 8; j++)
#pragma unroll
        for (int c = 0; c < 4; c++) o[j][c] = 0.0f;
    float m0 = -INFINITY, m1 = -INFINITY, l0 = 0.0f, l1 = 0.0f;

    // permuted column for V store: slot for key kk within 8-group
    const int kkl = lrow & 7;
    const int pcol = (lrow & 56) | (kkl >> 1) | ((kkl & 1) << 2);

    for (int kb = qb; kb < S_LEN / 64; kb++) {
        __syncthreads();   // previous tile's smem reads complete
        const int k0g = kb << 6;

        // load K tile -> Ks (row-major [key][d], tf32)
        {
            const float* src = K + base + (size_t)(k0g + lrow) * HD + lcol;
#pragma unroll
            for (int u = 0; u < 8; u++) {
                float4 v = *(const float4*)(src + (u << 2));
                uint4 t;
                t.x = cvt_tf32(v.x); t.y = cvt_tf32(v.y);
                t.z = cvt_tf32(v.z); t.w = cvt_tf32(v.w);
                *(uint4*)&Ks[lrow * 68 + lcol + (u << 2)] = t;
            }
        }
        // load V tile -> Vt (transposed [d][slot], key-permuted, tf32)
        {
            const float* src = V + base + (size_t)(k0g + lrow) * HD + lcol;
#pragma unroll
            for (int u = 0; u < 8; u++) {
                float4 v = *(const float4*)(src + (u << 2));
                const int d = lcol + (u << 2);
                Vt[(d + 0) * 68 + pcol] = cvt_tf32(v.x);
                Vt[(d + 1) * 68 + pcol] = cvt_tf32(v.y);
                Vt[(d + 2) * 68 + pcol] = cvt_tf32(v.z);
                Vt[(d + 3) * 68 + pcol] = cvt_tf32(v.w);
            }
        }
        __syncthreads();

        // S = Q @ K^T (exp2 domain; Q pre-scaled by 1/hd*log2e)
        float s[8][4];
#pragma unroll
        for (int j = 0; j < 8; j++)
#pragma unroll
            for (int c = 0; c < 4; c++) s[j][c] = 0.0f;

#pragma unroll
        for (int ks = 0; ks < 8; ks++) {
            uint32_t b[4][4];
#pragma unroll
            for (int j2 = 0; j2 < 4; j2++)
                ldm4(b[j2], sKs + (((j2 << 4) + row_off) * 68 + (ks << 3) + k_off) * 4);
#pragma unroll
            for (int j = 0; j < 8; j++)
                mma8(s[j], qa[ks][0], qa[ks][1], qa[ks][2], qa[ks][3],
                     b[j >> 1][(j & 1) << 1], b[j >> 1][((j & 1) << 1) + 1]);
        }

        // mask diagonal block: keep key >= q
        if (kb == qb) {
            const int r0l = (wid << 4) + tq;
#pragma unroll
            for (int j = 0; j < 8; j++) {
                const int c0 = (j << 3) + (tr << 1);
                if (c0 < r0l)     s[j][0] = -INFINITY;
                if (c0 + 1 < r0l) s[j][1] = -INFINITY;
                if (c0 < r0l + 8)     s[j][2] = -INFINITY;
                if (c0 + 1 < r0l + 8) s[j][3] = -INFINITY;
            }
        }

        // online softmax (rows tq and tq+8; replicated across 4 lanes)
        float rmax0 = -INFINITY, rmax1 = -INFINITY;
#pragma unroll
        for (int j = 0; j < 8; j++) {
            rmax0 = fmaxf(rmax0, fmaxf(s[j][0], s[j][1]));
            rmax1 = fmaxf(rmax1, fmaxf(s[j][2], s[j][3]));
        }
#pragma unroll
        for (int off = 1; off <= 2; off <<= 1) {
            rmax0 = fmaxf(rmax0, __shfl_xor_sync(0xffffffffu, rmax0, off));
            rmax1 = fmaxf(rmax1, __shfl_xor_sync(0xffffffffu, rmax1, off));
        }
        const float mn0 = fmaxf(m0, rmax0);
        const float mn1 = fmaxf(m1, rmax1);
        const float fac0 = ex2f(m0 - mn0);
        const float fac1 = ex2f(m1 - mn1);
        float sum0 = 0.0f, sum1 = 0.0f;
#pragma unroll
        for (int j = 0; j < 8; j++) {
            s[j][0] = ex2f(s[j][0] - mn0);
            s[j][1] = ex2f(s[j][1] - mn0);
            s[j][2] = ex2f(s[j][2] - mn1);
            s[j][3] = ex2f(s[j][3] - mn1);
            sum0 += s[j][0] + s[j][1];
            sum1 += s[j][2] + s[j][3];
        }
#pragma unroll
        for (int off = 1; off <= 2; off <<= 1) {
            sum0 += __shfl_xor_sync(0xffffffffu, sum0, off);
            sum1 += __shfl_xor_sync(0xffffffffu, sum1, off);
        }
        l0 = l0 * fac0 + sum0;  m0 = mn0;
        l1 = l1 * fac1 + sum1;  m1 = mn1;
#pragma unroll
        for (int j = 0; j < 8; j++) {
            o[j][0] *= fac0; o[j][1] *= fac0;
            o[j][2] *= fac1; o[j][3] *= fac1;
        }

        // O += P @ V, P directly from registers (V columns pre-permuted).
        // A-frag PTX order for key-group ks: (s0, s2, s1, s3) cvt'd to tf32.
#pragma unroll
        for (int ks = 0; ks < 8; ks++) {
            const uint32_t p0 = cvt_tf32(s[ks][0]);
            const uint32_t p1 = cvt_tf32(s[ks][2]);
            const uint32_t p2 = cvt_tf32(s[ks][1]);
            const uint32_t p3 = cvt_tf32(s[ks][3]);
            uint32_t b[4][4];
#pragma unroll
            for (int j2 = 0; j2 < 4; j2++)
                ldm4(b[j2], sVt + (((j2 << 4) + row_off) * 68 + (ks << 3) + k_off) * 4);
#pragma unroll
            for (int j = 0; j < 8; j++)
                mma8(o[j], p0, p1, p2, p3,
                     b[j >> 1][(j & 1) << 1], b[j >> 1][((j & 1) << 1) + 1]);
        }
    }

    // epilogue: normalize and write [B,S,D]
    const float inv0 = 1.0f / l0;
    const float inv1 = 1.0f / l1;
    const int b = bh >> 4;
    const int h = bh & 15;
    const int r0g = q0 + (wid << 4) + tq;
#pragma unroll
    for (int j = 0; j < 8; j++) {
        const int col = (h << 6) + (j << 3) + (tr << 1);
        *(float2*)&O[((size_t)(b * S_LEN + r0g)) * EDIM + col] =
            make_float2(o[j][0] * inv0, o[j][1] * inv0);
        *(float2*)&O[((size_t)(b * S_LEN + r0g + 8)) * EDIM + col] =
            make_float2(o[j][2] * inv1, o[j][3] * inv1);
    }
}

// ---------------------------------------------------------------------------
extern "C" void kernel_launch(void* const* d_in, const int* in_sizes, int n_in,
                              void* d_out, int out_size)
{
    (void)in_sizes; (void)n_in; (void)out_size;
    const float* x  = (const float*)d_in[0];
    const float* wq = (const float*)d_in[1];
    const float* bq = (const float*)d_in[2];
    const float* wk = (const float*)d_in[3];
    const float* bk = (const float*)d_in[4];
    const float* wv = (const float*)d_in[5];
    const float* bv = (const float*)d_in[6];
    const float* wo = (const float*)d_in[7];
    const float* bo = (const float*)d_in[8];
    float* out = (float*)d_out;

    float *qp, *kp, *vp, *ap;
    cudaGetSymbolAddress((void**)&qp, g_q);
    cudaGetSymbolAddress((void**)&kp, g_k);
    cudaGetSymbolAddress((void**)&vp, g_v);
    cudaGetSymbolAddress((void**)&ap, g_attn);

    dim3 ggrid(EDIM / 128, MROWS / 128);   // (8, 32)
    gemm_tc<<<ggrid, 256>>>(x, wq, bq, qp, 1, QSCALE);
    gemm_tc<<<ggrid, 256>>>(x, wk, bk, kp, 1, 1.0f);
    gemm_tc<<<ggrid, 256>>>(x, wv, bv, vp, 1, 1.0f);

    dim3 fgrid(S_LEN / 64, BATCH * NHEAD);   // (32, 32)
    flash_tc<<<fgrid, 128>>>(qp, kp, vp, ap);

    gemm_tc<<<ggrid, 256>>>(ap, wo, bo, out, 0, 1.0f);
}

// round 9
// speedup vs baseline: 2.8941x; 1.1008x over previous
#include <cuda_runtime.h>
#include <math.h>
#include <stdint.h>

#define S_LEN 2048
#define EDIM 1024
#define NHEAD 16
#define HD 64
#define BATCH 2
#define MROWS (BATCH * S_LEN)        // 4096
// softmax done in exp2 domain: fold 1/head_dim * log2(e) into Q projection
#define QSCALE (1.4426950408889634f / 64.0f)

// Scratch (device globals; no allocations allowed)
__device__ float g_q[BATCH * NHEAD * S_LEN * HD];   // [B,H,S,hd], pre-scaled
__device__ float g_k[BATCH * NHEAD * S_LEN * HD];
__device__ float g_v[BATCH * NHEAD * S_LEN * HD];
__device__ float g_attn[MROWS * EDIM];              // [B,S,D]

// GEMM smem: double buffer. As: 128x36/buf, Bs: 32x136/buf.
#define GA_STRIDE 36
#define GB_STRIDE 136
#define GA_WORDS (128 * GA_STRIDE)          // 4608
#define GB_WORDS (32 * GB_STRIDE)           // 4352
#define GEMM_SMEM_BYTES ((2 * GA_WORDS + 2 * GB_WORDS) * 4)   // 71680

// Flash smem: Ks double buffer (64x68 each) + Vt (64x68)
#define F_STRIDE 68
#define F_TILE_WORDS (64 * F_STRIDE)        // 4352
#define FLASH_SMEM_BYTES (3 * F_TILE_WORDS * 4)               // 52224

// ---------------------------------------------------------------------------
// helpers
// ---------------------------------------------------------------------------
__device__ __forceinline__ uint32_t cvt_tf32(float x) {
    uint32_t r;
    asm("cvt.rna.tf32.f32 %0, %1;" : "=r"(r) : "f"(x));
    return r;
}

__device__ __forceinline__ float ex2f(float x) {
    float y;
    asm("ex2.approx.ftz.f32 %0, %1;" : "=f"(y) : "f"(x));
    return y;
}

__device__ __forceinline__ void ldm4(uint32_t* r, uint32_t addr) {
    asm volatile("ldmatrix.sync.aligned.m8n8.x4.shared.b16 {%0,%1,%2,%3}, [%4];"
                 : "=r"(r[0]), "=r"(r[1]), "=r"(r[2]), "=r"(r[3]) : "r"(addr));
}

__device__ __forceinline__ void cp16(uint32_t smem_dst, const void* gsrc) {
    asm volatile("cp.async.cg.shared.global [%0], [%1], 16;"
                 :: "r"(smem_dst), "l"(gsrc));
}

__device__ __forceinline__ void cp_commit() {
    asm volatile("cp.async.commit_group;");
}

__device__ __forceinline__ void cp_wait1() {
    asm volatile("cp.async.wait_group 1;");
}

// c += A(16x8,tf32) * B(8x8,tf32); a0..a3 in PTX fragment order
__device__ __forceinline__ void mma8(float* c, uint32_t a0, uint32_t a1,
                                     uint32_t a2, uint32_t a3,
                                     uint32_t b0, uint32_t b1) {
    asm volatile(
        "mma.sync.aligned.m16n8k8.row.col.f32.tf32.tf32.f32 "
        "{%0,%1,%2,%3}, {%4,%5,%6,%7}, {%8,%9}, {%0,%1,%2,%3};\n"
        : "+f"(c[0]), "+f"(c[1]), "+f"(c[2]), "+f"(c[3])
        : "r"(a0), "r"(a1), "r"(a2), "r"(a3), "r"(b0), "r"(b1));
}

// ---------------------------------------------------------------------------
// GEMM: C[4096,1024] = A @ W + bias, tf32 tensor cores.
// 128x128 block, BK=32, 256 threads (8 warps, 2x4), warp tile 64x32.
// Double-buffered smem, ONE __syncthreads per k-iter.
// A: row-major smem (stride 36) + ldmatrix. B: k-major smem (stride 136,
// conflict-free float4 stores AND conflict-free b-frag LDS.32).
// mode 0: plain row-major store. mode 1: scatter to [B,H,S,hd] with scale.
// ---------------------------------------------------------------------------
__global__ __launch_bounds__(256) void gemm_tc(const float* __restrict__ A,
                                               const float* __restrict__ W,
                                               const float* __restrict__ bias,
                                               float* __restrict__ C,
                                               int mode, float scale)
{
    extern __shared__ uint32_t dyn[];
    // layout: As[buf0], As[buf1], Bs[buf0], Bs[buf1]

    const int tid = threadIdx.x;
    const int lane = tid & 31;
    const int wid = tid >> 5;
    const int wm = wid & 1;             // 2 warps along M
    const int wn = wid >> 1;            // 4 warps along N
    const int m0 = blockIdx.y << 7;
    const int n0 = blockIdx.x << 7;

    const int row_off = (lane & 7) + ((lane & 16) >> 1);
    const int k_off = (lane & 8) >> 1;
    const int cB = lane & 3;            // b-frag k row
    const int gB = lane >> 2;           // b-frag n col

    const uint32_t sBase = (uint32_t)__cvta_generic_to_shared(dyn);

    // global load assignments
    const int ar = tid >> 1;               // A row 0..127
    const int akc = (tid & 1) << 4;        // A k offset 0/16
    const int bkr = tid >> 3;              // W k row 0..31
    const int bnc = (tid & 7) << 4;        // W n offset 0..112

    const float* Ap = A + (size_t)(m0 + ar) * EDIM + akc;
    const float* Wp = W + (size_t)bkr * EDIM + n0 + bnc;

    float4 af[4], bf[4];
#pragma unroll
    for (int u = 0; u < 4; u++) {
        af[u] = *(const float4*)(Ap + (u << 2));
        bf[u] = *(const float4*)(Wp + (u << 2));
    }

    float acc[4][4][4];
#pragma unroll
    for (int i = 0; i < 4; i++)
#pragma unroll
        for (int j = 0; j < 4; j++)
#pragma unroll
            for (int c = 0; c < 4; c++) acc[i][j][c] = 0.0f;

    for (int k0 = 0; k0 < EDIM; k0 += 32) {
        const int b = (k0 >> 5) & 1;
        uint32_t* Asb = dyn + b * GA_WORDS;
        uint32_t* Bsb = dyn + 2 * GA_WORDS + b * GB_WORDS;

        // store current tile (tf32) into buffer b
#pragma unroll
        for (int u = 0; u < 4; u++) {
            uint4 t;
            t.x = cvt_tf32(af[u].x); t.y = cvt_tf32(af[u].y);
            t.z = cvt_tf32(af[u].z); t.w = cvt_tf32(af[u].w);
            *(uint4*)&Asb[ar * GA_STRIDE + akc + (u << 2)] = t;
        }
#pragma unroll
        for (int u = 0; u < 4; u++) {
            uint4 t;
            t.x = cvt_tf32(bf[u].x); t.y = cvt_tf32(bf[u].y);
            t.z = cvt_tf32(bf[u].z); t.w = cvt_tf32(bf[u].w);
            *(uint4*)&Bsb[bkr * GB_STRIDE + bnc + (u << 2)] = t;
        }

        // prefetch next tile from global (lands during compute)
        if (k0 + 32 < EDIM) {
#pragma unroll
            for (int u = 0; u < 4; u++) {
                af[u] = *(const float4*)(Ap + k0 + 32 + (u << 2));
                bf[u] = *(const float4*)(Wp + (size_t)(k0 + 32) * EDIM + (u << 2));
            }
        }

        __syncthreads();   // buffer b visible; prior reads of b finished last iter

        const uint32_t asA = sBase + (b * GA_WORDS) * 4;
        const uint32_t* bbase = dyn + 2 * GA_WORDS + b * GB_WORDS + (wn << 5) + gB;

#pragma unroll
        for (int ks = 0; ks < 32; ks += 8) {
            uint32_t a[4][4];
#pragma unroll
            for (int i = 0; i < 4; i++)
                ldm4(a[i], asA + (((wm << 6) + (i << 4) + row_off) * GA_STRIDE + ks + k_off) * 4);
            uint32_t bfrag[4][2];
#pragma unroll
            for (int j = 0; j < 4; j++) {
                bfrag[j][0] = bbase[(ks + cB) * GB_STRIDE + (j << 3)];
                bfrag[j][1] = bbase[(ks + cB + 4) * GB_STRIDE + (j << 3)];
            }
#pragma unroll
            for (int i = 0; i < 4; i++)
#pragma unroll
                for (int j = 0; j < 4; j++)
                    mma8(acc[i][j], a[i][0], a[i][2], a[i][1], a[i][3],
                         bfrag[j][0], bfrag[j][1]);
        }
        // no trailing sync: next iter writes the OTHER buffer
    }

    // epilogue: c0,c1 at (row tq, col 2tr..+1); c2,c3 at row tq+8
    const int tq = lane >> 2;
    const int tr = lane & 3;
#pragma unroll
    for (int i = 0; i < 4; i++) {
#pragma unroll
        for (int j = 0; j < 4; j++) {
            const int row = m0 + (wm << 6) + (i << 4) + tq;
            const int col = n0 + (wn << 5) + (j << 3) + (tr << 1);
            const float b0 = bias[col], b1 = bias[col + 1];
            if (mode == 0) {
                *(float2*)&C[(size_t)row * EDIM + col] =
                    make_float2(acc[i][j][0] + b0, acc[i][j][1] + b1);
                *(float2*)&C[(size_t)(row + 8) * EDIM + col] =
                    make_float2(acc[i][j][2] + b0, acc[i][j][3] + b1);
            } else {
                const int h = col >> 6, d = col & 63;
#pragma unroll
                for (int rr = 0; rr < 2; rr++) {
                    const int r = row + (rr << 3);
                    const int bb = r >> 11;
                    const int s = r & (S_LEN - 1);
                    size_t dst = ((size_t)((bb * NHEAD + h) * S_LEN + s)) * HD + d;
                    *(float2*)&C[dst] = make_float2(
                        (acc[i][j][(rr << 1) + 0] + b0) * scale,
                        (acc[i][j][(rr << 1) + 1] + b1) * scale);
                }
            }
        }
    }
}

// ---------------------------------------------------------------------------
// Flash attention (mask keeps j >= i), tf32 tensor cores, pipelined.
// Bq=Bk=64, 128 threads (4 warps), each warp owns 16 q rows.
// K: cp.async double-buffered ring (raw fp32 bits; tf32 truncation in MMA).
// V: global->regs issued before S-MMAs (latency hidden), cvt+permuted store.
// P stays in registers (FA-2 permuted-V trick).
// ---------------------------------------------------------------------------
__global__ __launch_bounds__(128) void flash_tc(const float* __restrict__ Q,
                                                const float* __restrict__ K,
                                                const float* __restrict__ V,
                                                float* __restrict__ O)
{
    extern __shared__ uint32_t dyn[];
    // layout: Ks[buf0] (4352 w), Ks[buf1] (4352 w), Vt (4352 w)
    uint32_t* Vt = dyn + 2 * F_TILE_WORDS;

    const int tid = threadIdx.x;
    const int lane = tid & 31;
    const int wid = tid >> 5;          // 0..3
    const int qb = blockIdx.x;
    const int bh = blockIdx.y;
    const int q0 = qb << 6;
    const size_t base = (size_t)bh * S_LEN * HD;

    const int row_off = (lane & 7) + ((lane & 16) >> 1);
    const int k_off = (lane & 8) >> 1;
    const int tq = lane >> 2;
    const int tr = lane & 3;

    const uint32_t sBase = (uint32_t)__cvta_generic_to_shared(dyn);
    const uint32_t sVt = sBase + (2 * F_TILE_WORDS) * 4;

    const int lrow = tid >> 1;               // 0..63
    const int lcol = (tid & 1) << 5;         // 0/32

    // Q fragments straight from global, PTX order (a0,a1,a2,a3)
    uint32_t qa[8][4];
    {
        const float* Qb = Q + base + (size_t)(q0 + (wid << 4) + tq) * HD;
#pragma unroll
        for (int ks = 0; ks < 8; ks++) {
            qa[ks][0] = cvt_tf32(Qb[(ks << 3) + tr]);
            qa[ks][1] = cvt_tf32(Qb[(HD << 3) + (ks << 3) + tr]);
            qa[ks][2] = cvt_tf32(Qb[(ks << 3) + tr + 4]);
            qa[ks][3] = cvt_tf32(Qb[(HD << 3) + (ks << 3) + tr + 4]);
        }
    }

    float o[8][4];
#pragma unroll
    for (int j = 0; j < 8; j++)
#pragma unroll
        for (int c = 0; c < 4; c++) o[j][c] = 0.0f;
    float m0 = -INFINITY, m1 = -INFINITY, l0 = 0.0f, l1 = 0.0f;

    // permuted column for V store: slot for key kk within 8-group
    const int kkl = lrow & 7;
    const int pcol = (lrow & 56) | (kkl >> 1) | ((kkl & 1) << 2);

    // prologue: prefetch K tile kb0=qb into buffer qb&1
    {
        const float* src = K + base + (size_t)(q0 + lrow) * HD + lcol;
        const uint32_t dst = sBase + (((qb & 1) * F_TILE_WORDS) + lrow * F_STRIDE + lcol) * 4;
#pragma unroll
        for (int u = 0; u < 8; u++)
            cp16(dst + (u << 4), src + (u << 2));
        cp_commit();
    }

    for (int kb = qb; kb < S_LEN / 64; kb++) {
        const int cur = kb & 1;
        const int k0g = kb << 6;

        // [A] V tile -> regs (latency hidden under S-MMAs + softmax)
        float4 vregs[8];
        {
            const float* vsrc = V + base + (size_t)(k0g + lrow) * HD + lcol;
#pragma unroll
            for (int u = 0; u < 8; u++)
                vregs[u] = *(const float4*)(vsrc + (u << 2));
        }

        // [B] prefetch next K tile into the other buffer
        if (kb + 1 < S_LEN / 64) {
            const float* src = K + base + (size_t)(k0g + 64 + lrow) * HD + lcol;
            const uint32_t dst = sBase + (((cur ^ 1) * F_TILE_WORDS) + lrow * F_STRIDE + lcol) * 4;
#pragma unroll
            for (int u = 0; u < 8; u++)
                cp16(dst + (u << 4), src + (u << 2));
        }
        cp_commit();

        cp_wait1();        // current K tile landed (this thread's part)
        __syncthreads();   // K[cur] visible to all; prior-tile PV reads done

        // [C] S = Q @ K^T (exp2 domain; Q pre-scaled by 1/hd*log2e)
        const uint32_t sKs = sBase + (cur * F_TILE_WORDS) * 4;
        float s[8][4];
#pragma unroll
        for (int j = 0; j < 8; j++)
#pragma unroll
            for (int c = 0; c < 4; c++) s[j][c] = 0.0f;

#pragma unroll
        for (int ks = 0; ks < 8; ks++) {
            uint32_t b[4][4];
#pragma unroll
            for (int j2 = 0; j2 < 4; j2++)
                ldm4(b[j2], sKs + (((j2 << 4) + row_off) * F_STRIDE + (ks << 3) + k_off) * 4);
#pragma unroll
            for (int j = 0; j < 8; j++)
                mma8(s[j], qa[ks][0], qa[ks][1], qa[ks][2], qa[ks][3],
                     b[j >> 1][(j & 1) << 1], b[j >> 1][((j & 1) << 1) + 1]);
        }

        // mask diagonal block: keep key >= q
        if (kb == qb) {
            const int r0l = (wid << 4) + tq;
#pragma unroll
            for (int j = 0; j < 8; j++) {
                const int c0 = (j << 3) + (tr << 1);
                if (c0 < r0l)     s[j][0] = -INFINITY;
                if (c0 + 1 < r0l) s[j][1] = -INFINITY;
                if (c0 < r0l + 8)     s[j][2] = -INFINITY;
                if (c0 + 1 < r0l + 8) s[j][3] = -INFINITY;
            }
        }

        // [D] online softmax (rows tq and tq+8; replicated across 4 lanes)
        float rmax0 = -INFINITY, rmax1 = -INFINITY;
#pragma unroll
        for (int j = 0; j < 8; j++) {
            rmax0 = fmaxf(rmax0, fmaxf(s[j][0], s[j][1]));
            rmax1 = fmaxf(rmax1, fmaxf(s[j][2], s[j][3]));
        }
#pragma unroll
        for (int off = 1; off <= 2; off <<= 1) {
            rmax0 = fmaxf(rmax0, __shfl_xor_sync(0xffffffffu, rmax0, off));
            rmax1 = fmaxf(rmax1, __shfl_xor_sync(0xffffffffu, rmax1, off));
        }
        const float mn0 = fmaxf(m0, rmax0);
        const float mn1 = fmaxf(m1, rmax1);
        const float fac0 = ex2f(m0 - mn0);
        const float fac1 = ex2f(m1 - mn1);
        float sum0 = 0.0f, sum1 = 0.0f;
#pragma unroll
        for (int j = 0; j < 8; j++) {
            s[j][0] = ex2f(s[j][0] - mn0);
            s[j][1] = ex2f(s[j][1] - mn0);
            s[j][2] = ex2f(s[j][2] - mn1);
            s[j][3] = ex2f(s[j][3] - mn1);
            sum0 += s[j][0] + s[j][1];
            sum1 += s[j][2] + s[j][3];
        }
#pragma unroll
        for (int off = 1; off <= 2; off <<= 1) {
            sum0 += __shfl_xor_sync(0xffffffffu, sum0, off);
            sum1 += __shfl_xor_sync(0xffffffffu, sum1, off);
        }
        l0 = l0 * fac0 + sum0;  m0 = mn0;
        l1 = l1 * fac1 + sum1;  m1 = mn1;
#pragma unroll
        for (int j = 0; j < 8; j++) {
            o[j][0] *= fac0; o[j][1] *= fac0;
            o[j][2] *= fac1; o[j][3] *= fac1;
        }

        // [F] store V tile transposed+permuted (vregs have landed by now)
#pragma unroll
        for (int u = 0; u < 8; u++) {
            const int d = lcol + (u << 2);
            Vt[(d + 0) * F_STRIDE + pcol] = cvt_tf32(vregs[u].x);
            Vt[(d + 1) * F_STRIDE + pcol] = cvt_tf32(vregs[u].y);
            Vt[(d + 2) * F_STRIDE + pcol] = cvt_tf32(vregs[u].z);
            Vt[(d + 3) * F_STRIDE + pcol] = cvt_tf32(vregs[u].w);
        }
        __syncthreads();   // Vt ready

        // [G] O += P @ V, P directly from registers (V columns pre-permuted).
        // A-frag PTX order for key-group ks: (s0, s2, s1, s3) cvt'd to tf32.
#pragma unroll
        for (int ks = 0; ks < 8; ks++) {
            const uint32_t p0 = cvt_tf32(s[ks][0]);
            const uint32_t p1 = cvt_tf32(s[ks][2]);
            const uint32_t p2 = cvt_tf32(s[ks][1]);
            const uint32_t p3 = cvt_tf32(s[ks][3]);
            uint32_t b[4][4];
#pragma unroll
            for (int j2 = 0; j2 < 4; j2++)
                ldm4(b[j2], sVt + (((j2 << 4) + row_off) * F_STRIDE + (ks << 3) + k_off) * 4);
#pragma unroll
            for (int j = 0; j < 8; j++)
                mma8(o[j], p0, p1, p2, p3,
                     b[j >> 1][(j & 1) << 1], b[j >> 1][((j & 1) << 1) + 1]);
        }
    }

    // epilogue: normalize and write [B,S,D]
    const float inv0 = 1.0f / l0;
    const float inv1 = 1.0f / l1;
    const int b = bh >> 4;
    const int h = bh & 15;
    const int r0g = q0 + (wid << 4) + tq;
#pragma unroll
    for (int j = 0; j < 8; j++) {
        const int col = (h << 6) + (j << 3) + (tr << 1);
        *(float2*)&O[((size_t)(b * S_LEN + r0g)) * EDIM + col] =
            make_float2(o[j][0] * inv0, o[j][1] * inv0);
        *(float2*)&O[((size_t)(b * S_LEN + r0g + 8)) * EDIM + col] =
            make_float2(o[j][2] * inv1, o[j][3] * inv1);
    }
}

// ---------------------------------------------------------------------------
extern "C" void kernel_launch(void* const* d_in, const int* in_sizes, int n_in,
                              void* d_out, int out_size)
{
    (void)in_sizes; (void)n_in; (void)out_size;
    const float* x  = (const float*)d_in[0];
    const float* wq = (const float*)d_in[1];
    const float* bq = (const float*)d_in[2];
    const float* wk = (const float*)d_in[3];
    const float* bk = (const float*)d_in[4];
    const float* wv = (const float*)d_in[5];
    const float* bv = (const float*)d_in[6];
    const float* wo = (const float*)d_in[7];
    const float* bo = (const float*)d_in[8];
    float* out = (float*)d_out;

    // idempotent opt-in for >48KB dynamic smem (host-side attr, not a stream op)
    cudaFuncSetAttribute(gemm_tc, cudaFuncAttributeMaxDynamicSharedMemorySize,
                         GEMM_SMEM_BYTES);
    cudaFuncSetAttribute(flash_tc, cudaFuncAttributeMaxDynamicSharedMemorySize,
                         FLASH_SMEM_BYTES);

    float *qp, *kp, *vp, *ap;
    cudaGetSymbolAddress((void**)&qp, g_q);
    cudaGetSymbolAddress((void**)&kp, g_k);
    cudaGetSymbolAddress((void**)&vp, g_v);
    cudaGetSymbolAddress((void**)&ap, g_attn);

    dim3 ggrid(EDIM / 128, MROWS / 128);   // (8, 32)
    gemm_tc<<<ggrid, 256, GEMM_SMEM_BYTES>>>(x, wq, bq, qp, 1, QSCALE);
    gemm_tc<<<ggrid, 256, GEMM_SMEM_BYTES>>>(x, wk, bk, kp, 1, 1.0f);
    gemm_tc<<<ggrid, 256, GEMM_SMEM_BYTES>>>(x, wv, bv, vp, 1, 1.0f);

    dim3 fgrid(S_LEN / 64, BATCH * NHEAD);   // (32, 32)
    flash_tc<<<fgrid, 128, FLASH_SMEM_BYTES>>>(qp, kp, vp, ap);

    gemm_tc<<<ggrid, 256, GEMM_SMEM_BYTES>>>(ap, wo, bo, out, 0, 1.0f);
}

// round 12
// speedup vs baseline: 5.1550x; 1.7812x over previous
#include <cuda_runtime.h>
#include <cuda_fp16.h>
#include <math.h>
#include <stdint.h>

#define S_LEN 2048
#define EDIM 1024
#define NHEAD 16
#define HD 64
#define BATCH 2
#define MROWS (BATCH * S_LEN)        // 4096
// softmax in exp2 domain: fold 1/head_dim * log2(e) into Q projection
#define QSCALE (1.4426950408889634f / 64.0f)

// Scratch (device globals; no allocations allowed) — all fp16
__device__ __half g_q[BATCH * NHEAD * S_LEN * HD];
__device__ __half g_k[BATCH * NHEAD * S_LEN * HD];
__device__ __half g_v[BATCH * NHEAD * S_LEN * HD];
__device__ __half g_attn[MROWS * EDIM];
__device__ __half g_xh[MROWS * EDIM];
__device__ __half g_wh[4 * EDIM * EDIM];

// GEMM smem: 3 stages. A: 128 rows x 40 halfs (10240B). B: 32 rows x 136 halfs (8704B).
#define GA_H 40
#define GB_H 136
#define G_STG 18944                       // 10240 + 8704
#define GEMM_SMEM (3 * G_STG)             // 56832
// Flash smem: 3 stages of (K 64x72 halfs + V 64x72 halfs); F_KV is BYTES per tile
#define F_H 72
#define F_KV 9216
#define F_STG (2 * F_KV)                  // 18432
#define FLASH_SMEM (3 * F_STG)            // 55296

// ---------------------------------------------------------------------------
// helpers
// ---------------------------------------------------------------------------
__device__ __forceinline__ float ex2f(float x) {
    float y;
    asm("ex2.approx.ftz.f32 %0, %1;" : "=f"(y) : "f"(x));
    return y;
}
__device__ __forceinline__ void ldm4(uint32_t* r, uint32_t addr) {
    asm volatile("ldmatrix.sync.aligned.m8n8.x4.shared.b16 {%0,%1,%2,%3}, [%4];"
                 : "=r"(r[0]), "=r"(r[1]), "=r"(r[2]), "=r"(r[3]) : "r"(addr));
}
__device__ __forceinline__ void ldm4t(uint32_t* r, uint32_t addr) {
    asm volatile("ldmatrix.sync.aligned.m8n8.x4.trans.shared.b16 {%0,%1,%2,%3}, [%4];"
                 : "=r"(r[0]), "=r"(r[1]), "=r"(r[2]), "=r"(r[3]) : "r"(addr));
}
__device__ __forceinline__ void cp16(uint32_t smem_dst, const void* gsrc) {
    asm volatile("cp.async.cg.shared.global [%0], [%1], 16;"
                 :: "r"(smem_dst), "l"(gsrc));
}
__device__ __forceinline__ void cp_commit() {
    asm volatile("cp.async.commit_group;");
}
// c += A(16x16 f16) * B(16x8 f16), fp32 accum
__device__ __forceinline__ void mma16(float* c, uint32_t a0, uint32_t a1,
                                      uint32_t a2, uint32_t a3,
                                      uint32_t b0, uint32_t b1) {
    asm volatile(
        "mma.sync.aligned.m16n8k16.row.col.f32.f16.f16.f32 "
        "{%0,%1,%2,%3}, {%4,%5,%6,%7}, {%8,%9}, {%0,%1,%2,%3};\n"
        : "+f"(c[0]), "+f"(c[1]), "+f"(c[2]), "+f"(c[3])
        : "r"(a0), "r"(a1), "r"(a2), "r"(a3), "r"(b0), "r"(b1));
}
__device__ __forceinline__ uint32_t h2u(float a, float b) {
    __half2 h = __floats2half2_rn(a, b);
    return *reinterpret_cast<uint32_t*>(&h);
}

// ---------------------------------------------------------------------------
// fp32 -> fp16 convert (contiguous)
// ---------------------------------------------------------------------------
__global__ __launch_bounds__(256) void conv_h(const float* __restrict__ src,
                                              __half* __restrict__ dst)
{
    const size_t i = ((size_t)blockIdx.x * 256 + threadIdx.x) * 4;
    float4 v = *(const float4*)(src + i);
    *(__half2*)(dst + i)     = __floats2half2_rn(v.x, v.y);
    *(__half2*)(dst + i + 2) = __floats2half2_rn(v.z, v.w);
}

// ---------------------------------------------------------------------------
// fp16 GEMM: C[4096,1024] = A @ W + bias. 128x128 block, BK=32, 256 threads
// (8 warps 2x4, warp tile 64x32). 3-stage cp.async ring, 1 sync/iter.
// A [m][k] smem stride 40 halfs (ldmatrix conflict-free).
// W [k][n] smem stride 136 halfs, B frags via ldmatrix.x4.trans.
// mode 0: fp32 row-major store. mode 1: fp16 scatter to [B,H,S,hd] * scale.
// ---------------------------------------------------------------------------
__global__ __launch_bounds__(256) void gemm_h(const __half* __restrict__ A,
                                              const __half* __restrict__ W,
                                              const float* __restrict__ bias,
                                              void* __restrict__ Cout,
                                              int mode, float scale)
{
    extern __shared__ __half sm[];
    const uint32_t sbase = (uint32_t)__cvta_generic_to_shared(sm);
    const int tid = threadIdx.x;
    const int lane = tid & 31;
    const int wid = tid >> 5;
    const int wm = wid & 1;
    const int wn = wid >> 1;
    const int m0 = blockIdx.y << 7;
    const int n0 = blockIdx.x << 7;

    // cp.async assignments (per-phase conflict-free)
    const int arow = tid & 63;          // + 64 on second step
    const int aseg = tid >> 6;          // 0..3, 8 halfs each
    const int brow = tid & 31;          // k row
    const int bseg = tid >> 5;          // 0..7 (+8), 8 halfs each

    const __half* ag = A + (size_t)(m0 + arow) * EDIM + aseg * 8;
    const __half* wg = W + (size_t)brow * EDIM + n0 + bseg * 8;

    auto issue = [&](int kc) {
        const int st = kc % 3;
        const uint32_t ab = sbase + st * G_STG;
        const uint32_t bb = ab + 10240;
        const __half* a = ag + (kc << 5);
        cp16(ab + (arow * GA_H + aseg * 8) * 2, a);
        cp16(ab + ((arow + 64) * GA_H + aseg * 8) * 2, a + (size_t)64 * EDIM);
        const __half* w = wg + (size_t)(kc << 5) * EDIM;
        cp16(bb + (brow * GB_H + bseg * 8) * 2, w);
        cp16(bb + (brow * GB_H + bseg * 8 + 64) * 2, w + 64);
        cp_commit();
    };

    float acc[4][4][4];
#pragma unroll
    for (int i = 0; i < 4; i++)
#pragma unroll
        for (int j = 0; j < 4; j++)
#pragma unroll
            for (int c = 0; c < 4; c++) acc[i][j][c] = 0.0f;

    issue(0);
    issue(1);

    const int lrow16 = lane & 15;
    const int lhi = (lane >> 4) << 3;

    for (int kc = 0; kc < 32; kc++) {
        if (kc < 31) asm volatile("cp.async.wait_group 1;");
        else         asm volatile("cp.async.wait_group 0;");
        __syncthreads();
        if (kc + 2 < 32) issue(kc + 2);

        const int st = kc % 3;
        const uint32_t ab = sbase + st * G_STG;
        const uint32_t bb = ab + 10240;

#pragma unroll
        for (int ks = 0; ks < 2; ks++) {
            uint32_t a[4][4];
#pragma unroll
            for (int i = 0; i < 4; i++)
                ldm4(a[i], ab + (((wm << 6) + (i << 4) + lrow16) * GA_H
                                 + (ks << 4) + lhi) * 2);
            uint32_t b[2][4];
#pragma unroll
            for (int jt = 0; jt < 2; jt++)
                ldm4t(b[jt], bb + (((ks << 4) + lrow16) * GB_H
                                   + (wn << 5) + (jt << 4) + lhi) * 2);
#pragma unroll
            for (int i = 0; i < 4; i++)
#pragma unroll
                for (int j = 0; j < 4; j++)
                    mma16(acc[i][j], a[i][0], a[i][1], a[i][2], a[i][3],
                          b[j >> 1][(j & 1) << 1], b[j >> 1][((j & 1) << 1) + 1]);
        }
    }

    // epilogue
    const int tq = lane >> 2;
    const int tr = lane & 3;
#pragma unroll
    for (int i = 0; i < 4; i++) {
#pragma unroll
        for (int j = 0; j < 4; j++) {
            const int row = m0 + (wm << 6) + (i << 4) + tq;
            const int col = n0 + (wn << 5) + (j << 3) + (tr << 1);
            const float b0 = bias[col], b1 = bias[col + 1];
            if (mode == 0) {
                float* C = (float*)Cout;
                *(float2*)&C[(size_t)row * EDIM + col] =
                    make_float2(acc[i][j][0] + b0, acc[i][j][1] + b1);
                *(float2*)&C[(size_t)(row + 8) * EDIM + col] =
                    make_float2(acc[i][j][2] + b0, acc[i][j][3] + b1);
            } else {
                __half* C = (__half*)Cout;
                const int h = col >> 6, d = col & 63;
#pragma unroll
                for (int rr = 0; rr < 2; rr++) {
                    const int r = row + (rr << 3);
                    const int bb2 = r >> 11;
                    const int s = r & (S_LEN - 1);
                    size_t dst = ((size_t)((bb2 * NHEAD + h) * S_LEN + s)) * HD + d;
                    *(__half2*)&C[dst] = __floats2half2_rn(
                        (acc[i][j][(rr << 1) + 0] + b0) * scale,
                        (acc[i][j][(rr << 1) + 1] + b1) * scale);
                }
            }
        }
    }
}

// ---------------------------------------------------------------------------
// fp16 flash attention (mask keeps j >= i). Bq=Bk=64, 128 threads (4 warps).
// K+V in one 3-stage cp.async ring, ONE sync per tile.
// S: Q(frags from global) @ K^T with B frags via non-trans ldmatrix on [key][d].
// P@V: P packed half2 in regs (native layout match), V via ldmatrix.trans.
// ---------------------------------------------------------------------------
__global__ __launch_bounds__(128) void flash_h(const __half* __restrict__ Q,
                                               const __half* __restrict__ K,
                                               const __half* __restrict__ V,
                                               __half* __restrict__ O)
{
    extern __shared__ __half smf[];
    const uint32_t sbase = (uint32_t)__cvta_generic_to_shared(smf);

    const int tid = threadIdx.x;
    const int lane = tid & 31;
    const int wid = tid >> 5;
    const int qb = blockIdx.x;
    const int bh = blockIdx.y;
    const int q0 = qb << 6;
    const size_t base = (size_t)bh * S_LEN * HD;

    const int tq = lane >> 2;
    const int tr = lane & 3;
    const int lrow16 = lane & 15;
    const int lhi = (lane >> 4) << 3;

    const int krow = tid & 63;
    const int kseg = tid >> 6;          // 0/1: halfs 0-31 / 32-63

    const int T = (S_LEN / 64) - qb;

    const __half* kg = K + base + (size_t)(q0 + krow) * HD + kseg * 32;
    const __half* vg = V + base + (size_t)(q0 + krow) * HD + kseg * 32;

    auto issue = [&](int t) {
        const int st = t % 3;
        const uint32_t kb = sbase + st * F_STG;
        const __half* ks_ = kg + ((size_t)t << 6) * HD;
        const __half* vs_ = vg + ((size_t)t << 6) * HD;
        const uint32_t doff = (krow * F_H + kseg * 32) * 2;
#pragma unroll
        for (int u = 0; u < 4; u++)
            cp16(kb + doff + (u << 4), ks_ + (u << 3));
#pragma unroll
        for (int u = 0; u < 4; u++)
            cp16(kb + F_KV + doff + (u << 4), vs_ + (u << 3));
        cp_commit();
    };

    // Q fragments from global fp16, PTX order
    uint32_t qa[4][4];
    {
        const __half* Qr = Q + base + (size_t)(q0 + (wid << 4) + tq) * HD;
#pragma unroll
        for (int ks = 0; ks < 4; ks++) {
            qa[ks][0] = *(const uint32_t*)(Qr + (ks << 4) + (tr << 1));
            qa[ks][1] = *(const uint32_t*)(Qr + (HD << 3) + (ks << 4) + (tr << 1));
            qa[ks][2] = *(const uint32_t*)(Qr + (ks << 4) + 8 + (tr << 1));
            qa[ks][3] = *(const uint32_t*)(Qr + (HD << 3) + (ks << 4) + 8 + (tr << 1));
        }
    }

    float o[8][4];
#pragma unroll
    for (int j = 0; j < 8; j++)
#pragma unroll
        for (int c = 0; c < 4; c++) o[j][c] = 0.0f;
    float m0 = -INFINITY, m1 = -INFINITY, l0 = 0.0f, l1 = 0.0f;

    issue(0);
    if (T > 1) issue(1);

    for (int t = 0; t < T; t++) {
        if (t + 1 < T) asm volatile("cp.async.wait_group 1;");
        else           asm volatile("cp.async.wait_group 0;");
        __syncthreads();
        if (t + 2 < T) issue(t + 2);

        const int st = t % 3;
        const uint32_t sK = sbase + st * F_STG;
        const uint32_t sV = sK + F_KV;

        // S = Q @ K^T
        float s[8][4];
#pragma unroll
        for (int j = 0; j < 8; j++)
#pragma unroll
            for (int c = 0; c < 4; c++) s[j][c] = 0.0f;

#pragma unroll
        for (int ks = 0; ks < 4; ks++) {
            uint32_t b[4][4];
#pragma unroll
            for (int kt = 0; kt < 4; kt++)
                ldm4(b[kt], sK + (((kt << 4) + lrow16) * F_H + (ks << 4) + lhi) * 2);
#pragma unroll
            for (int kt = 0; kt < 4; kt++) {
                mma16(s[(kt << 1) + 0], qa[ks][0], qa[ks][1], qa[ks][2], qa[ks][3],
                      b[kt][0], b[kt][2]);
                mma16(s[(kt << 1) + 1], qa[ks][0], qa[ks][1], qa[ks][2], qa[ks][3],
                      b[kt][1], b[kt][3]);
            }
        }

        // mask diagonal block: keep key >= q
        if (t == 0) {
            const int r0l = (wid << 4) + tq;
#pragma unroll
            for (int j = 0; j < 8; j++) {
                const int c0 = (j << 3) + (tr << 1);
                if (c0 < r0l)     s[j][0] = -INFINITY;
                if (c0 + 1 < r0l) s[j][1] = -INFINITY;
                if (c0 < r0l + 8)     s[j][2] = -INFINITY;
                if (c0 + 1 < r0l + 8) s[j][3] = -INFINITY;
            }
        }

        // online softmax
        float rmax0 = -INFINITY, rmax1 = -INFINITY;
#pragma unroll
        for (int j = 0; j < 8; j++) {
            rmax0 = fmaxf(rmax0, fmaxf(s[j][0], s[j][1]));
            rmax1 = fmaxf(rmax1, fmaxf(s[j][2], s[j][3]));
        }
#pragma unroll
        for (int off = 1; off <= 2; off <<= 1) {
            rmax0 = fmaxf(rmax0, __shfl_xor_sync(0xffffffffu, rmax0, off));
            rmax1 = fmaxf(rmax1, __shfl_xor_sync(0xffffffffu, rmax1, off));
        }
        const float mn0 = fmaxf(m0, rmax0);
        const float mn1 = fmaxf(m1, rmax1);
        const float fac0 = ex2f(m0 - mn0);
        const float fac1 = ex2f(m1 - mn1);
        float sum0 = 0.0f, sum1 = 0.0f;
#pragma unroll
        for (int j = 0; j < 8; j++) {
            s[j][0] = ex2f(s[j][0] - mn0);
            s[j][1] = ex2f(s[j][1] - mn0);
            s[j][2] = ex2f(s[j][2] - mn1);
            s[j][3] = ex2f(s[j][3] - mn1);
            sum0 += s[j][0] + s[j][1];
            sum1 += s[j][2] + s[j][3];
        }
#pragma unroll
        for (int off = 1; off <= 2; off <<= 1) {
            sum0 += __shfl_xor_sync(0xffffffffu, sum0, off);
            sum1 += __shfl_xor_sync(0xffffffffu, sum1, off);
        }
        l0 = l0 * fac0 + sum0;  m0 = mn0;
        l1 = l1 * fac1 + sum1;  m1 = mn1;
#pragma unroll
        for (int j = 0; j < 8; j++) {
            o[j][0] *= fac0; o[j][1] *= fac0;
            o[j][2] *= fac1; o[j][3] *= fac1;
        }

        // O += P @ V : P packed to half2 (native A-frag layout), V via trans
#pragma unroll
        for (int g = 0; g < 4; g++) {
            const uint32_t p0 = h2u(s[(g << 1)][0],     s[(g << 1)][1]);
            const uint32_t p1 = h2u(s[(g << 1)][2],     s[(g << 1)][3]);
            const uint32_t p2 = h2u(s[(g << 1) + 1][0], s[(g << 1) + 1][1]);
            const uint32_t p3 = h2u(s[(g << 1) + 1][2], s[(g << 1) + 1][3]);
#pragma unroll
            for (int dt = 0; dt < 4; dt++) {
                uint32_t b[4];
                ldm4t(b, sV + (((g << 4) + lrow16) * F_H + (dt << 4) + lhi) * 2);
                mma16(o[(dt << 1) + 0], p0, p1, p2, p3, b[0], b[1]);
                mma16(o[(dt << 1) + 1], p0, p1, p2, p3, b[2], b[3]);
            }
        }
    }

    // epilogue: normalize, write fp16 [B,S,D]
    const float inv0 = 1.0f / l0;
    const float inv1 = 1.0f / l1;
    const int b = bh >> 4;
    const int h = bh & 15;
    const int r0g = q0 + (wid << 4) + tq;
#pragma unroll
    for (int j = 0; j < 8; j++) {
        const int col = (h << 6) + (j << 3) + (tr << 1);
        *(__half2*)&O[((size_t)(b * S_LEN + r0g)) * EDIM + col] =
            __floats2half2_rn(o[j][0] * inv0, o[j][1] * inv0);
        *(__half2*)&O[((size_t)(b * S_LEN + r0g + 8)) * EDIM + col] =
            __floats2half2_rn(o[j][2] * inv1, o[j][3] * inv1);
    }
}

// ---------------------------------------------------------------------------
extern "C" void kernel_launch(void* const* d_in, const int* in_sizes, int n_in,
                              void* d_out, int out_size)
{
    (void)in_sizes; (void)n_in; (void)out_size;
    const float* x  = (const float*)d_in[0];
    const float* wq = (const float*)d_in[1];
    const float* bq = (const float*)d_in[2];
    const float* wk = (const float*)d_in[3];
    const float* bk = (const float*)d_in[4];
    const float* wv = (const float*)d_in[5];
    const float* bv = (const float*)d_in[6];
    const float* wo = (const float*)d_in[7];
    const float* bo = (const float*)d_in[8];
    float* out = (float*)d_out;

    cudaFuncSetAttribute(gemm_h, cudaFuncAttributeMaxDynamicSharedMemorySize,
                         GEMM_SMEM);
    cudaFuncSetAttribute(flash_h, cudaFuncAttributeMaxDynamicSharedMemorySize,
                         FLASH_SMEM);

    __half *qp, *kp, *vp, *ap, *xh, *wh;
    cudaGetSymbolAddress((void**)&qp, g_q);
    cudaGetSymbolAddress((void**)&kp, g_k);
    cudaGetSymbolAddress((void**)&vp, g_v);
    cudaGetSymbolAddress((void**)&ap, g_attn);
    cudaGetSymbolAddress((void**)&xh, g_xh);
    cudaGetSymbolAddress((void**)&wh, g_wh);

    const size_t WSZ = (size_t)EDIM * EDIM;
    conv_h<<<MROWS * EDIM / 1024, 256>>>(x, xh);
    conv_h<<<WSZ / 1024, 256>>>(wq, wh + 0 * WSZ);
    conv_h<<<WSZ / 1024, 256>>>(wk, wh + 1 * WSZ);
    conv_h<<<WSZ / 1024, 256>>>(wv, wh + 2 * WSZ);
    conv_h<<<WSZ / 1024, 256>>>(wo, wh + 3 * WSZ);

    dim3 ggrid(EDIM / 128, MROWS / 128);   // (8, 32)
    gemm_h<<<ggrid, 256, GEMM_SMEM>>>(xh, wh + 0 * WSZ, bq, qp, 1, QSCALE);
    gemm_h<<<ggrid, 256, GEMM_SMEM>>>(xh, wh + 1 * WSZ, bk, kp, 1, 1.0f);
    gemm_h<<<ggrid, 256, GEMM_SMEM>>>(xh, wh + 2 * WSZ, bv, vp, 1, 1.0f);

    dim3 fgrid(S_LEN / 64, BATCH * NHEAD);   // (32, 32)
    flash_h<<<fgrid, 128, FLASH_SMEM>>>(qp, kp, vp, ap);

    gemm_h<<<ggrid, 256, GEMM_SMEM>>>(ap, wh + 3 * WSZ, bo, out, 0, 1.0f);
}

// round 13
// speedup vs baseline: 5.9290x; 1.1502x over previous
#include <cuda_runtime.h>
#include <cuda_fp16.h>
#include <math.h>
#include <stdint.h>

#define S_LEN 2048
#define EDIM 1024
#define NHEAD 16
#define HD 64
#define BATCH 2
#define MROWS (BATCH * S_LEN)        // 4096
// softmax in exp2 domain: fold 1/head_dim * log2(e) into Q projection
#define QSCALE (1.4426950408889634f / 64.0f)

// Scratch (device globals; no allocations allowed) — all fp16
__device__ __half g_q[BATCH * NHEAD * S_LEN * HD];
__device__ __half g_k[BATCH * NHEAD * S_LEN * HD];
__device__ __half g_v[BATCH * NHEAD * S_LEN * HD];
__device__ __half g_attn[MROWS * EDIM];
__device__ __half g_xh[MROWS * EDIM];
__device__ __half g_wh[4 * EDIM * EDIM];

// GEMM smem: 3 stages. A: 128 rows x 40 halfs (10240B). B: 32 rows x 136 halfs (8704B).
#define GA_H 40
#define GB_H 136
#define G_STG 18944                       // 10240 + 8704
#define GEMM_SMEM (3 * G_STG)             // 56832
// Flash smem: 3 stages of (K 64x72 halfs + V 64x72 halfs); F_KV is BYTES per tile
#define F_H 72
#define F_KV 9216
#define F_STG (2 * F_KV)                  // 18432
#define FLASH_SMEM (3 * F_STG)            // 55296

// ---------------------------------------------------------------------------
// helpers
// ---------------------------------------------------------------------------
__device__ __forceinline__ float ex2f(float x) {
    float y;
    asm("ex2.approx.ftz.f32 %0, %1;" : "=f"(y) : "f"(x));
    return y;
}
__device__ __forceinline__ void ldm4(uint32_t* r, uint32_t addr) {
    asm volatile("ldmatrix.sync.aligned.m8n8.x4.shared.b16 {%0,%1,%2,%3}, [%4];"
                 : "=r"(r[0]), "=r"(r[1]), "=r"(r[2]), "=r"(r[3]) : "r"(addr));
}
__device__ __forceinline__ void ldm4t(uint32_t* r, uint32_t addr) {
    asm volatile("ldmatrix.sync.aligned.m8n8.x4.trans.shared.b16 {%0,%1,%2,%3}, [%4];"
                 : "=r"(r[0]), "=r"(r[1]), "=r"(r[2]), "=r"(r[3]) : "r"(addr));
}
__device__ __forceinline__ void cp16(uint32_t smem_dst, const void* gsrc) {
    asm volatile("cp.async.cg.shared.global [%0], [%1], 16;"
                 :: "r"(smem_dst), "l"(gsrc));
}
__device__ __forceinline__ void cp_commit() {
    asm volatile("cp.async.commit_group;");
}
// c += A(16x16 f16) * B(16x8 f16), fp32 accum
__device__ __forceinline__ void mma16(float* c, uint32_t a0, uint32_t a1,
                                      uint32_t a2, uint32_t a3,
                                      uint32_t b0, uint32_t b1) {
    asm volatile(
        "mma.sync.aligned.m16n8k16.row.col.f32.f16.f16.f32 "
        "{%0,%1,%2,%3}, {%4,%5,%6,%7}, {%8,%9}, {%0,%1,%2,%3};\n"
        : "+f"(c[0]), "+f"(c[1]), "+f"(c[2]), "+f"(c[3])
        : "r"(a0), "r"(a1), "r"(a2), "r"(a3), "r"(b0), "r"(b1));
}
__device__ __forceinline__ uint32_t h2u(float a, float b) {
    __half2 h = __floats2half2_rn(a, b);
    return *reinterpret_cast<uint32_t*>(&h);
}

// ---------------------------------------------------------------------------
// fused fp32 -> fp16 convert: x (4096 blks), then wq/wk/wv/wo (1024 blks each)
// ---------------------------------------------------------------------------
__global__ __launch_bounds__(256) void conv_all(const float* __restrict__ x,
                                                const float* __restrict__ wq,
                                                const float* __restrict__ wk,
                                                const float* __restrict__ wv,
                                                const float* __restrict__ wo,
                                                __half* __restrict__ xh,
                                                __half* __restrict__ wh)
{
    const int bx = blockIdx.x;
    const float* src;
    __half* dst;
    size_t off;
    if (bx < 4096) {
        src = x; dst = xh; off = (size_t)bx * 1024;
    } else {
        const int z = (bx - 4096) >> 10;
        src = (z == 0) ? wq : (z == 1) ? wk : (z == 2) ? wv : wo;
        dst = wh + (size_t)z * EDIM * EDIM;
        off = (size_t)((bx - 4096) & 1023) * 1024;
    }
    const size_t i = off + threadIdx.x * 4;
    float4 v = *(const float4*)(src + i);
    *(__half2*)(dst + i)     = __floats2half2_rn(v.x, v.y);
    *(__half2*)(dst + i + 2) = __floats2half2_rn(v.z, v.w);
}

// ---------------------------------------------------------------------------
// fp16 GEMM core (device inline): C tile = A[m0..,:] @ W[:, n0..] + bias
// 128x128 block, BK=32, 256 threads, 3-stage cp.async ring.
// ---------------------------------------------------------------------------
__device__ __forceinline__ void gemm_body(const __half* __restrict__ A,
                                          const __half* __restrict__ W,
                                          const float* __restrict__ bias,
                                          void* __restrict__ Cout,
                                          int m0, int n0, int mode, float scale)
{
    extern __shared__ __half sm[];
    const uint32_t sbase = (uint32_t)__cvta_generic_to_shared(sm);
    const int tid = threadIdx.x;
    const int lane = tid & 31;
    const int wid = tid >> 5;
    const int wm = wid & 1;
    const int wn = wid >> 1;

    const int arow = tid & 63;
    const int aseg = tid >> 6;
    const int brow = tid & 31;
    const int bseg = tid >> 5;

    const __half* ag = A + (size_t)(m0 + arow) * EDIM + aseg * 8;
    const __half* wg = W + (size_t)brow * EDIM + n0 + bseg * 8;

    auto issue = [&](int kc) {
        const int st = kc % 3;
        const uint32_t ab = sbase + st * G_STG;
        const uint32_t bb = ab + 10240;
        const __half* a = ag + (kc << 5);
        cp16(ab + (arow * GA_H + aseg * 8) * 2, a);
        cp16(ab + ((arow + 64) * GA_H + aseg * 8) * 2, a + (size_t)64 * EDIM);
        const __half* w = wg + (size_t)(kc << 5) * EDIM;
        cp16(bb + (brow * GB_H + bseg * 8) * 2, w);
        cp16(bb + (brow * GB_H + bseg * 8 + 64) * 2, w + 64);
        cp_commit();
    };

    float acc[4][4][4];
#pragma unroll
    for (int i = 0; i < 4; i++)
#pragma unroll
        for (int j = 0; j < 4; j++)
#pragma unroll
            for (int c = 0; c < 4; c++) acc[i][j][c] = 0.0f;

    issue(0);
    issue(1);

    const int lrow16 = lane & 15;
    const int lhi = (lane >> 4) << 3;

    for (int kc = 0; kc < 32; kc++) {
        if (kc < 31) asm volatile("cp.async.wait_group 1;");
        else         asm volatile("cp.async.wait_group 0;");
        __syncthreads();
        if (kc + 2 < 32) issue(kc + 2);

        const int st = kc % 3;
        const uint32_t ab = sbase + st * G_STG;
        const uint32_t bb = ab + 10240;

#pragma unroll
        for (int ks = 0; ks < 2; ks++) {
            uint32_t a[4][4];
#pragma unroll
            for (int i = 0; i < 4; i++)
                ldm4(a[i], ab + (((wm << 6) + (i << 4) + lrow16) * GA_H
                                 + (ks << 4) + lhi) * 2);
            uint32_t b[2][4];
#pragma unroll
            for (int jt = 0; jt < 2; jt++)
                ldm4t(b[jt], bb + (((ks << 4) + lrow16) * GB_H
                                   + (wn << 5) + (jt << 4) + lhi) * 2);
#pragma unroll
            for (int i = 0; i < 4; i++)
#pragma unroll
                for (int j = 0; j < 4; j++)
                    mma16(acc[i][j], a[i][0], a[i][1], a[i][2], a[i][3],
                          b[j >> 1][(j & 1) << 1], b[j >> 1][((j & 1) << 1) + 1]);
        }
    }

    const int tq = lane >> 2;
    const int tr = lane & 3;
#pragma unroll
    for (int i = 0; i < 4; i++) {
#pragma unroll
        for (int j = 0; j < 4; j++) {
            const int row = m0 + (wm << 6) + (i << 4) + tq;
            const int col = n0 + (wn << 5) + (j << 3) + (tr << 1);
            const float b0 = bias[col], b1 = bias[col + 1];
            if (mode == 0) {
                float* C = (float*)Cout;
                *(float2*)&C[(size_t)row * EDIM + col] =
                    make_float2(acc[i][j][0] + b0, acc[i][j][1] + b1);
                *(float2*)&C[(size_t)(row + 8) * EDIM + col] =
                    make_float2(acc[i][j][2] + b0, acc[i][j][3] + b1);
            } else {
                __half* C = (__half*)Cout;
                const int h = col >> 6, d = col & 63;
#pragma unroll
                for (int rr = 0; rr < 2; rr++) {
                    const int r = row + (rr << 3);
                    const int bb2 = r >> 11;
                    const int s = r & (S_LEN - 1);
                    size_t dst = ((size_t)((bb2 * NHEAD + h) * S_LEN + s)) * HD + d;
                    *(__half2*)&C[dst] = __floats2half2_rn(
                        (acc[i][j][(rr << 1) + 0] + b0) * scale,
                        (acc[i][j][(rr << 1) + 1] + b1) * scale);
                }
            }
        }
    }
}

// fused Q/K/V projection: grid.x = 24 (8 n-blocks x 3 weights)
__global__ __launch_bounds__(256) void gemm_qkv(const __half* __restrict__ A,
                                                const __half* __restrict__ wh,
                                                const float* __restrict__ bq,
                                                const float* __restrict__ bk,
                                                const float* __restrict__ bv,
                                                __half* __restrict__ qp,
                                                __half* __restrict__ kp,
                                                __half* __restrict__ vp)
{
    const int z = blockIdx.x >> 3;
    const int n0 = (blockIdx.x & 7) << 7;
    const int m0 = blockIdx.y << 7;
    const __half* W = wh + (size_t)z * EDIM * EDIM;
    const float* bias = (z == 0) ? bq : (z == 1) ? bk : bv;
    __half* out = (z == 0) ? qp : (z == 1) ? kp : vp;
    gemm_body(A, W, bias, out, m0, n0, 1, (z == 0) ? (float)QSCALE : 1.0f);
}

// output projection
__global__ __launch_bounds__(256) void gemm_out(const __half* __restrict__ A,
                                                const __half* __restrict__ W,
                                                const float* __restrict__ bias,
                                                float* __restrict__ out)
{
    gemm_body(A, W, bias, out, blockIdx.y << 7, blockIdx.x << 7, 0, 1.0f);
}

// ---------------------------------------------------------------------------
// fp16 flash attention (mask keeps j >= i). Bq=128, Bk=64, 256 threads
// (8 warps x 16 q rows). K+V in one 3-stage cp.async ring, ONE sync per tile.
// Warp-group wg = wid>>2 owns q 64-block (2qb+wg); it skips t < wg (fully
// masked) and applies the triangular mask at t == wg.
// ---------------------------------------------------------------------------
__global__ __launch_bounds__(256) void flash_h(const __half* __restrict__ Q,
                                               const __half* __restrict__ K,
                                               const __half* __restrict__ V,
                                               __half* __restrict__ O)
{
    extern __shared__ __half smf[];
    const uint32_t sbase = (uint32_t)__cvta_generic_to_shared(smf);

    const int tid = threadIdx.x;
    const int lane = tid & 31;
    const int wid = tid >> 5;          // 0..7
    const int wg = wid >> 2;           // 0/1: q rows 0-63 / 64-127
    const int qb = blockIdx.x;         // 0..15 (q block of 128 rows)
    const int bh = blockIdx.y;
    const int q0 = qb << 7;
    const size_t base = (size_t)bh * S_LEN * HD;

    const int tq = lane >> 2;
    const int tr = lane & 3;
    const int lrow16 = lane & 15;
    const int lhi = (lane >> 4) << 3;

    // K/V tile staging: 64 rows x 128B; 512 chunks of 16B per tile; 2/thread
    const int T = (S_LEN / 64) - (qb << 1);

    auto issue = [&](int t) {
        const int st = t % 3;
        const uint32_t kb = sbase + st * F_STG;
        const size_t gbase = base + (((size_t)(qb << 1) + t) << 6) * HD;
#pragma unroll
        for (int i = 0; i < 2; i++) {
            const int c = tid + (i << 8);       // 0..511
            const int row = c >> 3;
            const int seg = (c & 7) << 3;       // halfs
            const uint32_t doff = (row * F_H + seg) * 2;
            cp16(kb + doff, K + gbase + (size_t)row * HD + seg);
            cp16(kb + F_KV + doff, V + gbase + (size_t)row * HD + seg);
        }
        cp_commit();
    };

    // Q fragments from global fp16, PTX order
    uint32_t qa[4][4];
    {
        const __half* Qr = Q + base + (size_t)(q0 + (wid << 4) + tq) * HD;
#pragma unroll
        for (int ks = 0; ks < 4; ks++) {
            qa[ks][0] = *(const uint32_t*)(Qr + (ks << 4) + (tr << 1));
            qa[ks][1] = *(const uint32_t*)(Qr + (HD << 3) + (ks << 4) + (tr << 1));
            qa[ks][2] = *(const uint32_t*)(Qr + (ks << 4) + 8 + (tr << 1));
            qa[ks][3] = *(const uint32_t*)(Qr + (HD << 3) + (ks << 4) + 8 + (tr << 1));
        }
    }

    float o[8][4];
#pragma unroll
    for (int j = 0; j < 8; j++)
#pragma unroll
        for (int c = 0; c < 4; c++) o[j][c] = 0.0f;
    float m0 = -INFINITY, m1 = -INFINITY, l0 = 0.0f, l1 = 0.0f;

    issue(0);
    if (T > 1) issue(1);

    for (int t = 0; t < T; t++) {
        if (t + 1 < T) asm volatile("cp.async.wait_group 1;");
        else           asm volatile("cp.async.wait_group 0;");
        __syncthreads();
        if (t + 2 < T) issue(t + 2);

        if (t < wg) continue;   // fully masked tile for this warp-group

        const int st = t % 3;
        const uint32_t sK = sbase + st * F_STG;
        const uint32_t sV = sK + F_KV;

        // S = Q @ K^T
        float s[8][4];
#pragma unroll
        for (int j = 0; j < 8; j++)
#pragma unroll
            for (int c = 0; c < 4; c++) s[j][c] = 0.0f;

#pragma unroll
        for (int ks = 0; ks < 4; ks++) {
            uint32_t b[4][4];
#pragma unroll
            for (int kt = 0; kt < 4; kt++)
                ldm4(b[kt], sK + (((kt << 4) + lrow16) * F_H + (ks << 4) + lhi) * 2);
#pragma unroll
            for (int kt = 0; kt < 4; kt++) {
                mma16(s[(kt << 1) + 0], qa[ks][0], qa[ks][1], qa[ks][2], qa[ks][3],
                      b[kt][0], b[kt][2]);
                mma16(s[(kt << 1) + 1], qa[ks][0], qa[ks][1], qa[ks][2], qa[ks][3],
                      b[kt][1], b[kt][3]);
            }
        }

        // diagonal block: keep key >= q (local row within this 64-block)
        if (t == wg) {
            const int r0l = ((wid & 3) << 4) + tq;
#pragma unroll
            for (int j = 0; j < 8; j++) {
                const int c0 = (j << 3) + (tr << 1);
                if (c0 < r0l)     s[j][0] = -INFINITY;
                if (c0 + 1 < r0l) s[j][1] = -INFINITY;
                if (c0 < r0l + 8)     s[j][2] = -INFINITY;
                if (c0 + 1 < r0l + 8) s[j][3] = -INFINITY;
            }
        }

        // online softmax
        float rmax0 = -INFINITY, rmax1 = -INFINITY;
#pragma unroll
        for (int j = 0; j < 8; j++) {
            rmax0 = fmaxf(rmax0, fmaxf(s[j][0], s[j][1]));
            rmax1 = fmaxf(rmax1, fmaxf(s[j][2], s[j][3]));
        }
#pragma unroll
        for (int off = 1; off <= 2; off <<= 1) {
            rmax0 = fmaxf(rmax0, __shfl_xor_sync(0xffffffffu, rmax0, off));
            rmax1 = fmaxf(rmax1, __shfl_xor_sync(0xffffffffu, rmax1, off));
        }
        const float mn0 = fmaxf(m0, rmax0);
        const float mn1 = fmaxf(m1, rmax1);
        const float fac0 = ex2f(m0 - mn0);
        const float fac1 = ex2f(m1 - mn1);
        float sum0 = 0.0f, sum1 = 0.0f;
#pragma unroll
        for (int j = 0; j < 8; j++) {
            s[j][0] = ex2f(s[j][0] - mn0);
            s[j][1] = ex2f(s[j][1] - mn0);
            s[j][2] = ex2f(s[j][2] - mn1);
            s[j][3] = ex2f(s[j][3] - mn1);
            sum0 += s[j][0] + s[j][1];
            sum1 += s[j][2] + s[j][3];
        }
#pragma unroll
        for (int off = 1; off <= 2; off <<= 1) {
            sum0 += __shfl_xor_sync(0xffffffffu, sum0, off);
            sum1 += __shfl_xor_sync(0xffffffffu, sum1, off);
        }
        l0 = l0 * fac0 + sum0;  m0 = mn0;
        l1 = l1 * fac1 + sum1;  m1 = mn1;
#pragma unroll
        for (int j = 0; j < 8; j++) {
            o[j][0] *= fac0; o[j][1] *= fac0;
            o[j][2] *= fac1; o[j][3] *= fac1;
        }

        // O += P @ V : P packed to half2 (native A-frag layout), V via trans
#pragma unroll
        for (int g = 0; g < 4; g++) {
            const uint32_t p0 = h2u(s[(g << 1)][0],     s[(g << 1)][1]);
            const uint32_t p1 = h2u(s[(g << 1)][2],     s[(g << 1)][3]);
            const uint32_t p2 = h2u(s[(g << 1) + 1][0], s[(g << 1) + 1][1]);
            const uint32_t p3 = h2u(s[(g << 1) + 1][2], s[(g << 1) + 1][3]);
#pragma unroll
            for (int dt = 0; dt < 4; dt++) {
                uint32_t b[4];
                ldm4t(b, sV + (((g << 4) + lrow16) * F_H + (dt << 4) + lhi) * 2);
                mma16(o[(dt << 1) + 0], p0, p1, p2, p3, b[0], b[1]);
                mma16(o[(dt << 1) + 1], p0, p1, p2, p3, b[2], b[3]);
            }
        }
    }

    // epilogue: normalize, write fp16 [B,S,D]
    const float inv0 = 1.0f / l0;
    const float inv1 = 1.0f / l1;
    const int b = bh >> 4;
    const int h = bh & 15;
    const int r0g = q0 + (wid << 4) + tq;
#pragma unroll
    for (int j = 0; j < 8; j++) {
        const int col = (h << 6) + (j << 3) + (tr << 1);
        *(__half2*)&O[((size_t)(b * S_LEN + r0g)) * EDIM + col] =
            __floats2half2_rn(o[j][0] * inv0, o[j][1] * inv0);
        *(__half2*)&O[((size_t)(b * S_LEN + r0g + 8)) * EDIM + col] =
            __floats2half2_rn(o[j][2] * inv1, o[j][3] * inv1);
    }
}

// ---------------------------------------------------------------------------
extern "C" void kernel_launch(void* const* d_in, const int* in_sizes, int n_in,
                              void* d_out, int out_size)
{
    (void)in_sizes; (void)n_in; (void)out_size;
    const float* x  = (const float*)d_in[0];
    const float* wq = (const float*)d_in[1];
    const float* bq = (const float*)d_in[2];
    const float* wk = (const float*)d_in[3];
    const float* bk = (const float*)d_in[4];
    const float* wv = (const float*)d_in[5];
    const float* bv = (const float*)d_in[6];
    const float* wo = (const float*)d_in[7];
    const float* bo = (const float*)d_in[8];
    float* out = (float*)d_out;

    cudaFuncSetAttribute(gemm_qkv, cudaFuncAttributeMaxDynamicSharedMemorySize,
                         GEMM_SMEM);
    cudaFuncSetAttribute(gemm_out, cudaFuncAttributeMaxDynamicSharedMemorySize,
                         GEMM_SMEM);
    cudaFuncSetAttribute(flash_h, cudaFuncAttributeMaxDynamicSharedMemorySize,
                         FLASH_SMEM);

    __half *qp, *kp, *vp, *ap, *xh, *wh;
    cudaGetSymbolAddress((void**)&qp, g_q);
    cudaGetSymbolAddress((void**)&kp, g_k);
    cudaGetSymbolAddress((void**)&vp, g_v);
    cudaGetSymbolAddress((void**)&ap, g_attn);
    cudaGetSymbolAddress((void**)&xh, g_xh);
    cudaGetSymbolAddress((void**)&wh, g_wh);

    conv_all<<<4096 + 4 * 1024, 256>>>(x, wq, wk, wv, wo, xh, wh);

    gemm_qkv<<<dim3(24, MROWS / 128), 256, GEMM_SMEM>>>(xh, wh, bq, bk, bv,
                                                        qp, kp, vp);

    flash_h<<<dim3(S_LEN / 128, BATCH * NHEAD), 256, FLASH_SMEM>>>(qp, kp, vp, ap);

    gemm_out<<<dim3(8, MROWS / 128), 256, GEMM_SMEM>>>(
        ap, wh + 3 * (size_t)EDIM * EDIM, bo, out);
}

// round 16
// speedup vs baseline: 6.5758x; 1.1091x over previous
#include <cuda_runtime.h>
#include <cuda_fp16.h>
#include <math.h>
#include <stdint.h>

#define S_LEN 2048
#define EDIM 1024
#define NHEAD 16
#define HD 64
#define BATCH 2
#define MROWS (BATCH * S_LEN)        // 4096
// softmax in exp2 domain: fold 1/head_dim * log2(e) into Q projection
#define QSCALE (1.4426950408889634f / 64.0f)

// Scratch (device globals; no allocations allowed) — all fp16
__device__ __half g_q[BATCH * NHEAD * S_LEN * HD];
__device__ __half g_k[BATCH * NHEAD * S_LEN * HD];
__device__ __half g_v[BATCH * NHEAD * S_LEN * HD];
__device__ __half g_attn[MROWS * EDIM];
__device__ __half g_xh[MROWS * EDIM];
__device__ __half g_wh[4 * EDIM * EDIM];

// GEMM smem: 3 stages, BK=64. A: 128 rows x 72 halfs (18432B). B: 64 rows x 136 halfs (17408B).
#define GA_H 72
#define GB_H 136
#define GA_B 18432
#define G_STG 35840                       // 18432 + 17408
#define GEMM_SMEM (3 * G_STG)             // 107520
// Flash smem: 3 stages of (K 64x72 halfs + V 64x72 halfs); F_KV is BYTES per tile
#define F_H 72
#define F_KV 9216
#define F_STG (2 * F_KV)                  // 18432
#define FLASH_SMEM (3 * F_STG)            // 55296

// ---------------------------------------------------------------------------
// helpers
// ---------------------------------------------------------------------------
__device__ __forceinline__ float ex2f(float x) {
    float y;
    asm("ex2.approx.ftz.f32 %0, %1;" : "=f"(y) : "f"(x));
    return y;
}
__device__ __forceinline__ void ldm4(uint32_t* r, uint32_t addr) {
    asm volatile("ldmatrix.sync.aligned.m8n8.x4.shared.b16 {%0,%1,%2,%3}, [%4];"
                 : "=r"(r[0]), "=r"(r[1]), "=r"(r[2]), "=r"(r[3]) : "r"(addr));
}
__device__ __forceinline__ void ldm4t(uint32_t* r, uint32_t addr) {
    asm volatile("ldmatrix.sync.aligned.m8n8.x4.trans.shared.b16 {%0,%1,%2,%3}, [%4];"
                 : "=r"(r[0]), "=r"(r[1]), "=r"(r[2]), "=r"(r[3]) : "r"(addr));
}
__device__ __forceinline__ void cp16(uint32_t smem_dst, const void* gsrc) {
    asm volatile("cp.async.cg.shared.global [%0], [%1], 16;"
                 :: "r"(smem_dst), "l"(gsrc));
}
__device__ __forceinline__ void cp_commit() {
    asm volatile("cp.async.commit_group;");
}
// c += A(16x16 f16) * B(16x8 f16), fp32 accum
__device__ __forceinline__ void mma16(float* c, uint32_t a0, uint32_t a1,
                                      uint32_t a2, uint32_t a3,
                                      uint32_t b0, uint32_t b1) {
    asm volatile(
        "mma.sync.aligned.m16n8k16.row.col.f32.f16.f16.f32 "
        "{%0,%1,%2,%3}, {%4,%5,%6,%7}, {%8,%9}, {%0,%1,%2,%3};\n"
        : "+f"(c[0]), "+f"(c[1]), "+f"(c[2]), "+f"(c[3])
        : "r"(a0), "r"(a1), "r"(a2), "r"(a3), "r"(b0), "r"(b1));
}
__device__ __forceinline__ uint32_t h2u(float a, float b) {
    __half2 h = __floats2half2_rn(a, b);
    return *reinterpret_cast<uint32_t*>(&h);
}

// ---------------------------------------------------------------------------
// fused fp32 -> fp16 convert: x (4096 blks), then wq/wk/wv/wo (1024 blks each)
// ---------------------------------------------------------------------------
__global__ __launch_bounds__(256) void conv_all(const float* __restrict__ x,
                                                const float* __restrict__ wq,
                                                const float* __restrict__ wk,
                                                const float* __restrict__ wv,
                                                const float* __restrict__ wo,
                                                __half* __restrict__ xh,
                                                __half* __restrict__ wh)
{
    const int bx = blockIdx.x;
    const float* src;
    __half* dst;
    size_t off;
    if (bx < 4096) {
        src = x; dst = xh; off = (size_t)bx * 1024;
    } else {
        const int z = (bx - 4096) >> 10;
        src = (z == 0) ? wq : (z == 1) ? wk : (z == 2) ? wv : wo;
        dst = wh + (size_t)z * EDIM * EDIM;
        off = (size_t)((bx - 4096) & 1023) * 1024;
    }
    const size_t i = off + threadIdx.x * 4;
    float4 v = *(const float4*)(src + i);
    *(__half2*)(dst + i)     = __floats2half2_rn(v.x, v.y);
    *(__half2*)(dst + i + 2) = __floats2half2_rn(v.z, v.w);
}

// ---------------------------------------------------------------------------
// fp16 GEMM core: C tile = A[m0..,:] @ W[:, n0..] + bias
// 128x128 block, BK=64, 256 threads (8 warps 2x4, warp tile 64x32),
// 3-stage cp.async ring, 1 sync per 64-k chunk (16 total).
// ---------------------------------------------------------------------------
__device__ __forceinline__ void gemm_body(const __half* __restrict__ A,
                                          const __half* __restrict__ W,
                                          const float* __restrict__ bias,
                                          void* __restrict__ Cout,
                                          int m0, int n0, int mode, float scale)
{
    extern __shared__ __half sm[];
    const uint32_t sbase = (uint32_t)__cvta_generic_to_shared(sm);
    const int tid = threadIdx.x;
    const int lane = tid & 31;
    const int wid = tid >> 5;
    const int wm = wid & 1;
    const int wn = wid >> 1;

    // cp.async assignments: A 128x64 halfs (2 thr/row, 32-half segs);
    // B 64x128 halfs (4 thr/row, 32-half segs); 4 chunks of 8 halfs each.
    const int arow = tid >> 1;
    const int aseg = (tid & 1) << 5;
    const int brow = tid >> 2;
    const int bseg = (tid & 3) << 5;

    const __half* ag = A + (size_t)(m0 + arow) * EDIM + aseg;
    const __half* wg = W + (size_t)brow * EDIM + n0 + bseg;

    auto issue = [&](int kc) {
        const int st = kc % 3;
        const uint32_t ab = sbase + st * G_STG;
        const uint32_t bb = ab + GA_B;
        const __half* a = ag + (kc << 6);
        const __half* w = wg + (size_t)(kc << 6) * EDIM;
#pragma unroll
        for (int u = 0; u < 4; u++)
            cp16(ab + (arow * GA_H + aseg + (u << 3)) * 2, a + (u << 3));
#pragma unroll
        for (int u = 0; u < 4; u++)
            cp16(bb + (brow * GB_H + bseg + (u << 3)) * 2, w + (u << 3));
        cp_commit();
    };

    float acc[4][4][4];
#pragma unroll
    for (int i = 0; i < 4; i++)
#pragma unroll
        for (int j = 0; j < 4; j++)
#pragma unroll
            for (int c = 0; c < 4; c++) acc[i][j][c] = 0.0f;

    issue(0);
    issue(1);

    const int lrow16 = lane & 15;
    const int lhi = (lane >> 4) << 3;

    for (int kc = 0; kc < 16; kc++) {
        if (kc < 15) asm volatile("cp.async.wait_group 1;");
        else         asm volatile("cp.async.wait_group 0;");
        __syncthreads();
        if (kc + 2 < 16) issue(kc + 2);

        const int st = kc % 3;
        const uint32_t ab = sbase + st * G_STG;
        const uint32_t bb = ab + GA_B;

#pragma unroll
        for (int ks = 0; ks < 4; ks++) {
            uint32_t a[4][4];
#pragma unroll
            for (int i = 0; i < 4; i++)
                ldm4(a[i], ab + (((wm << 6) + (i << 4) + lrow16) * GA_H
                                 + (ks << 4) + lhi) * 2);
            uint32_t b[2][4];
#pragma unroll
            for (int jt = 0; jt < 2; jt++)
                ldm4t(b[jt], bb + (((ks << 4) + lrow16) * GB_H
                                   + (wn << 5) + (jt << 4) + lhi) * 2);
#pragma unroll
            for (int i = 0; i < 4; i++)
#pragma unroll
                for (int j = 0; j < 4; j++)
                    mma16(acc[i][j], a[i][0], a[i][1], a[i][2], a[i][3],
                          b[j >> 1][(j & 1) << 1], b[j >> 1][((j & 1) << 1) + 1]);
        }
    }

    const int tq = lane >> 2;
    const int tr = lane & 3;
#pragma unroll
    for (int i = 0; i < 4; i++) {
#pragma unroll
        for (int j = 0; j < 4; j++) {
            const int row = m0 + (wm << 6) + (i << 4) + tq;
            const int col = n0 + (wn << 5) + (j << 3) + (tr << 1);
            const float b0 = bias[col], b1 = bias[col + 1];
            if (mode == 0) {
                float* C = (float*)Cout;
                *(float2*)&C[(size_t)row * EDIM + col] =
                    make_float2(acc[i][j][0] + b0, acc[i][j][1] + b1);
                *(float2*)&C[(size_t)(row + 8) * EDIM + col] =
                    make_float2(acc[i][j][2] + b0, acc[i][j][3] + b1);
            } else {
                __half* C = (__half*)Cout;
                const int h = col >> 6, d = col & 63;
#pragma unroll
                for (int rr = 0; rr < 2; rr++) {
                    const int r = row + (rr << 3);
                    const int bb2 = r >> 11;
                    const int s = r & (S_LEN - 1);
                    size_t dst = ((size_t)((bb2 * NHEAD + h) * S_LEN + s)) * HD + d;
                    *(__half2*)&C[dst] = __floats2half2_rn(
                        (acc[i][j][(rr << 1) + 0] + b0) * scale,
                        (acc[i][j][(rr << 1) + 1] + b1) * scale);
                }
            }
        }
    }
}

// fused Q/K/V projection: grid.x = 24 (8 n-blocks x 3 weights)
__global__ __launch_bounds__(256) void gemm_qkv(const __half* __restrict__ A,
                                                const __half* __restrict__ wh,
                                                const float* __restrict__ bq,
                                                const float* __restrict__ bk,
                                                const float* __restrict__ bv,
                                                __half* __restrict__ qp,
                                                __half* __restrict__ kp,
                                                __half* __restrict__ vp)
{
    const int z = blockIdx.x >> 3;
    const int n0 = (blockIdx.x & 7) << 7;
    const int m0 = blockIdx.y << 7;
    const __half* W = wh + (size_t)z * EDIM * EDIM;
    const float* bias = (z == 0) ? bq : (z == 1) ? bk : bv;
    __half* out = (z == 0) ? qp : (z == 1) ? kp : vp;
    gemm_body(A, W, bias, out, m0, n0, 1, (z == 0) ? (float)QSCALE : 1.0f);
}

// output projection
__global__ __launch_bounds__(256) void gemm_out(const __half* __restrict__ A,
                                                const __half* __restrict__ W,
                                                const float* __restrict__ bias,
                                                float* __restrict__ out)
{
    gemm_body(A, W, bias, out, blockIdx.y << 7, blockIdx.x << 7, 0, 1.0f);
}

// ---------------------------------------------------------------------------
// fp16 flash attention (mask keeps j >= i). Bq=128, Bk=64, 256 threads
// (8 warps x 16 q rows). K+V in one 3-stage cp.async ring, ONE sync per tile.
// Warp-group wg = wid>>2 owns q 64-block (2qb+wg); it skips t < wg (fully
// masked) and applies the triangular mask at t == wg.
// ---------------------------------------------------------------------------
__global__ __launch_bounds__(256) void flash_h(const __half* __restrict__ Q,
                                               const __half* __restrict__ K,
                                               const __half* __restrict__ V,
                                               __half* __restrict__ O)
{
    extern __shared__ __half smf[];
    const uint32_t sbase = (uint32_t)__cvta_generic_to_shared(smf);

    const int tid = threadIdx.x;
    const int lane = tid & 31;
    const int wid = tid >> 5;          // 0..7
    const int wg = wid >> 2;           // 0/1: q rows 0-63 / 64-127
    const int qb = blockIdx.x;         // 0..15 (q block of 128 rows)
    const int bh = blockIdx.y;
    const int q0 = qb << 7;
    const size_t base = (size_t)bh * S_LEN * HD;

    const int tq = lane >> 2;
    const int tr = lane & 3;
    const int lrow16 = lane & 15;
    const int lhi = (lane >> 4) << 3;

    const int T = (S_LEN / 64) - (qb << 1);

    auto issue = [&](int t) {
        const int st = t % 3;
        const uint32_t kb = sbase + st * F_STG;
        const size_t gbase = base + (((size_t)(qb << 1) + t) << 6) * HD;
#pragma unroll
        for (int i = 0; i < 2; i++) {
            const int c = tid + (i << 8);       // 0..511
            const int row = c >> 3;
            const int seg = (c & 7) << 3;       // halfs
            const uint32_t doff = (row * F_H + seg) * 2;
            cp16(kb + doff, K + gbase + (size_t)row * HD + seg);
            cp16(kb + F_KV + doff, V + gbase + (size_t)row * HD + seg);
        }
        cp_commit();
    };

    // Q fragments from global fp16, PTX order
    uint32_t qa[4][4];
    {
        const __half* Qr = Q + base + (size_t)(q0 + (wid << 4) + tq) * HD;
#pragma unroll
        for (int ks = 0; ks < 4; ks++) {
            qa[ks][0] = *(const uint32_t*)(Qr + (ks << 4) + (tr << 1));
            qa[ks][1] = *(const uint32_t*)(Qr + (HD << 3) + (ks << 4) + (tr << 1));
            qa[ks][2] = *(const uint32_t*)(Qr + (ks << 4) + 8 + (tr << 1));
            qa[ks][3] = *(const uint32_t*)(Qr + (HD << 3) + (ks << 4) + 8 + (tr << 1));
        }
    }

    float o[8][4];
#pragma unroll
    for (int j = 0; j < 8; j++)
#pragma unroll
        for (int c = 0; c < 4; c++) o[j][c] = 0.0f;
    float m0 = -INFINITY, m1 = -INFINITY, l0 = 0.0f, l1 = 0.0f;

    issue(0);
    if (T > 1) issue(1);

    for (int t = 0; t < T; t++) {
        if (t + 1 < T) asm volatile("cp.async.wait_group 1;");
        else           asm volatile("cp.async.wait_group 0;");
        __syncthreads();
        if (t + 2 < T) issue(t + 2);

        if (t < wg) continue;   // fully masked tile for this warp-group

        const int st = t % 3;
        const uint32_t sK = sbase + st * F_STG;
        const uint32_t sV = sK + F_KV;

        // S = Q @ K^T
        float s[8][4];
#pragma unroll
        for (int j = 0; j < 8; j++)
#pragma unroll
            for (int c = 0; c < 4; c++) s[j][c] = 0.0f;

#pragma unroll
        for (int ks = 0; ks < 4; ks++) {
            uint32_t b[4][4];
#pragma unroll
            for (int kt = 0; kt < 4; kt++)
                ldm4(b[kt], sK + (((kt << 4) + lrow16) * F_H + (ks << 4) + lhi) * 2);
#pragma unroll
            for (int kt = 0; kt < 4; kt++) {
                mma16(s[(kt << 1) + 0], qa[ks][0], qa[ks][1], qa[ks][2], qa[ks][3],
                      b[kt][0], b[kt][2]);
                mma16(s[(kt << 1) + 1], qa[ks][0], qa[ks][1], qa[ks][2], qa[ks][3],
                      b[kt][1], b[kt][3]);
            }
        }

        // diagonal block: keep key >= q (local row within this 64-block)
        if (t == wg) {
            const int r0l = ((wid & 3) << 4) + tq;
#pragma unroll
            for (int j = 0; j < 8; j++) {
                const int c0 = (j << 3) + (tr << 1);
                if (c0 < r0l)     s[j][0] = -INFINITY;
                if (c0 + 1 < r0l) s[j][1] = -INFINITY;
                if (c0 < r0l + 8)     s[j][2] = -INFINITY;
                if (c0 + 1 < r0l + 8) s[j][3] = -INFINITY;
            }
        }

        // online softmax
        float rmax0 = -INFINITY, rmax1 = -INFINITY;
#pragma unroll
        for (int j = 0; j < 8; j++) {
            rmax0 = fmaxf(rmax0, fmaxf(s[j][0], s[j][1]));
            rmax1 = fmaxf(rmax1, fmaxf(s[j][2], s[j][3]));
        }
#pragma unroll
        for (int off = 1; off <= 2; off <<= 1) {
            rmax0 = fmaxf(rmax0, __shfl_xor_sync(0xffffffffu, rmax0, off));
            rmax1 = fmaxf(rmax1, __shfl_xor_sync(0xffffffffu, rmax1, off));
        }
        const float mn0 = fmaxf(m0, rmax0);
        const float mn1 = fmaxf(m1, rmax1);
        const float fac0 = ex2f(m0 - mn0);
        const float fac1 = ex2f(m1 - mn1);
        float sum0 = 0.0f, sum1 = 0.0f;
#pragma unroll
        for (int j = 0; j < 8; j++) {
            s[j][0] = ex2f(s[j][0] - mn0);
            s[j][1] = ex2f(s[j][1] - mn0);
            s[j][2] = ex2f(s[j][2] - mn1);
            s[j][3] = ex2f(s[j][3] - mn1);
            sum0 += s[j][0] + s[j][1];
            sum1 += s[j][2] + s[j][3];
        }
#pragma unroll
        for (int off = 1; off <= 2; off <<= 1) {
            sum0 += __shfl_xor_sync(0xffffffffu, sum0, off);
            sum1 += __shfl_xor_sync(0xffffffffu, sum1, off);
        }
        l0 = l0 * fac0 + sum0;  m0 = mn0;
        l1 = l1 * fac1 + sum1;  m1 = mn1;
#pragma unroll
        for (int j = 0; j < 8; j++) {
            o[j][0] *= fac0; o[j][1] *= fac0;
            o[j][2] *= fac1; o[j][3] *= fac1;
        }

        // O += P @ V : P packed to half2 (native A-frag layout), V via trans
#pragma unroll
        for (int g = 0; g < 4; g++) {
            const uint32_t p0 = h2u(s[(g << 1)][0],     s[(g << 1)][1]);
            const uint32_t p1 = h2u(s[(g << 1)][2],     s[(g << 1)][3]);
            const uint32_t p2 = h2u(s[(g << 1) + 1][0], s[(g << 1) + 1][1]);
            const uint32_t p3 = h2u(s[(g << 1) + 1][2], s[(g << 1) + 1][3]);
#pragma unroll
            for (int dt = 0; dt < 4; dt++) {
                uint32_t b[4];
                ldm4t(b, sV + (((g << 4) + lrow16) * F_H + (dt << 4) + lhi) * 2);
                mma16(o[(dt << 1) + 0], p0, p1, p2, p3, b[0], b[1]);
                mma16(o[(dt << 1) + 1], p0, p1, p2, p3, b[2], b[3]);
            }
        }
    }

    // epilogue: normalize, write fp16 [B,S,D]
    const float inv0 = 1.0f / l0;
    const float inv1 = 1.0f / l1;
    const int b = bh >> 4;
    const int h = bh & 15;
    const int r0g = q0 + (wid << 4) + tq;
#pragma unroll
    for (int j = 0; j < 8; j++) {
        const int col = (h << 6) + (j << 3) + (tr << 1);
        *(__half2*)&O[((size_t)(b * S_LEN + r0g)) * EDIM + col] =
            __floats2half2_rn(o[j][0] * inv0, o[j][1] * inv0);
        *(__half2*)&O[((size_t)(b * S_LEN + r0g + 8)) * EDIM + col] =
            __floats2half2_rn(o[j][2] * inv1, o[j][3] * inv1);
    }
}

// ---------------------------------------------------------------------------
extern "C" void kernel_launch(void* const* d_in, const int* in_sizes, int n_in,
                              void* d_out, int out_size)
{
    (void)in_sizes; (void)n_in; (void)out_size;
    const float* x  = (const float*)d_in[0];
    const float* wq = (const float*)d_in[1];
    const float* bq = (const float*)d_in[2];
    const float* wk = (const float*)d_in[3];
    const float* bk = (const float*)d_in[4];
    const float* wv = (const float*)d_in[5];
    const float* bv = (const float*)d_in[6];
    const float* wo = (const float*)d_in[7];
    const float* bo = (const float*)d_in[8];
    float* out = (float*)d_out;

    cudaFuncSetAttribute(gemm_qkv, cudaFuncAttributeMaxDynamicSharedMemorySize,
                         GEMM_SMEM);
    cudaFuncSetAttribute(gemm_out, cudaFuncAttributeMaxDynamicSharedMemorySize,
                         GEMM_SMEM);
    cudaFuncSetAttribute(flash_h, cudaFuncAttributeMaxDynamicSharedMemorySize,
                         FLASH_SMEM);

    __half *qp, *kp, *vp, *ap, *xh, *wh;
    cudaGetSymbolAddress((void**)&qp, g_q);
    cudaGetSymbolAddress((void**)&kp, g_k);
    cudaGetSymbolAddress((void**)&vp, g_v);
    cudaGetSymbolAddress((void**)&ap, g_attn);
    cudaGetSymbolAddress((void**)&xh, g_xh);
    cudaGetSymbolAddress((void**)&wh, g_wh);

    conv_all<<<4096 + 4 * 1024, 256>>>(x, wq, wk, wv, wo, xh, wh);

    gemm_qkv<<<dim3(24, MROWS / 128), 256, GEMM_SMEM>>>(xh, wh, bq, bk, bv,
                                                        qp, kp, vp);

    flash_h<<<dim3(S_LEN / 128, BATCH * NHEAD), 256, FLASH_SMEM>>>(qp, kp, vp, ap);

    gemm_out<<<dim3(8, MROWS / 128), 256, GEMM_SMEM>>>(
        ap, wh + 3 * (size_t)EDIM * EDIM, bo, out);
}